// round 12
// baseline (speedup 1.0000x reference)
#include <cuda_runtime.h>
#include <cuda_fp16.h>
#include <cstdint>

// Problem constants
#define MROWS 8192
#define DM 512

// ---------------- scratch (static device arrays; no cudaMalloc allowed) ----
static __device__ __half g_x16[MROWS*DM];
static __device__ __half g_hp16[MROWS*DM];   // pre-LN h (fp16)
static __device__ __half g_h16[MROWS*DM];    // post-LN h (fp16)
static __device__ __half g_q16[MROWS*DM], g_k16[MROWS*DM], g_v16[MROWS*DM];
static __device__ __half g_c16[MROWS*DM];    // attention ctx
static __device__ __half g_h2_16[MROWS*DM];  // relu(ctx@Wo+bo)
// fp16 transposed weights ([n,k] so D = A·B^T = A·W)
static __device__ __half g_ww[DM*DM], g_wq[DM*DM], g_wk[DM*DM], g_wv[DM*DM], g_wo[DM*DM];

__device__ __forceinline__ uint32_t s2u(const void* p){
  return (uint32_t)__cvta_generic_to_shared(p);
}

// ---------------- mma.sync helpers -----------------------------------------
__device__ __forceinline__ void ldsm4(uint32_t* r, uint32_t addr){
  asm volatile("ldmatrix.sync.aligned.m8n8.x4.shared.b16 {%0,%1,%2,%3}, [%4];"
   : "=r"(r[0]),"=r"(r[1]),"=r"(r[2]),"=r"(r[3]) : "r"(addr));
}
__device__ __forceinline__ void ldsm4t(uint32_t* r, uint32_t addr){
  asm volatile("ldmatrix.sync.aligned.m8n8.x4.trans.shared.b16 {%0,%1,%2,%3}, [%4];"
   : "=r"(r[0]),"=r"(r[1]),"=r"(r[2]),"=r"(r[3]) : "r"(addr));
}
__device__ __forceinline__ void mma16816(float* d, const uint32_t* a, const uint32_t* b){
  asm volatile("mma.sync.aligned.m16n8k16.row.col.f32.f16.f16.f32 "
    "{%0,%1,%2,%3}, {%4,%5,%6,%7}, {%8,%9}, {%0,%1,%2,%3};"
    : "+f"(d[0]),"+f"(d[1]),"+f"(d[2]),"+f"(d[3])
    : "r"(a[0]),"r"(a[1]),"r"(a[2]),"r"(a[3]), "r"(b[0]),"r"(b[1]));
}

// fast exp: fp32 accuracy ~2.4e-6, runs on fma/alu pipes (no MUFU)
__device__ __forceinline__ float fexp(float x){
  float y = x * 1.44269504f;
  int   ki = __float2int_rn(y);
  float f  = y - (float)ki;
  float p = 1.333355815e-3f;
  p = fmaf(p, f, 9.618129107e-3f);
  p = fmaf(p, f, 5.550410866e-2f);
  p = fmaf(p, f, 2.402265069e-1f);
  p = fmaf(p, f, 6.931471806e-1f);
  p = fmaf(p, f, 1.0f);
  return p * __int_as_float((ki + 127) << 23);
}

// ---------------- GEMM core: CTA tile 256x128, warp tile 64x64, fp16 -------
// C16[8192,512] = A @ W^T(+bias). BK=64, 8 warps (4x2), 3-stage cp.async ring.
#define SA 72
#define A2BYTES (256*SA*2)           // 36864
#define B2BYTES (128*SA*2)           // 18432
#define STG2 (A2BYTES + B2BYTES)     // 55296
#define NSTG 3
#define GEMM_SMEM (NSTG*STG2)        // 165888
#define NC 8

struct GemmCore {
  uint32_t sbase;
  int m0, n0, tid, lane, warpM, warpN;
  float acc[4][8][4];

  __device__ __forceinline__ void init(uint32_t sb, int m0_, int n0_){
    sbase = sb; m0 = m0_; n0 = n0_;
    tid = threadIdx.x; lane = tid & 31;
    int wid = tid >> 5; warpM = wid >> 1; warpN = wid & 1;
#pragma unroll
    for (int i=0;i<4;i++)
#pragma unroll
      for (int j=0;j<8;j++)
#pragma unroll
        for (int r=0;r<4;r++) acc[i][j][r]=0.f;
  }

  __device__ __forceinline__ void load_chunk(int s, int c,
      const __half* A, const __half* W){
    const int kk0 = c * 64;
    const uint32_t da = sbase + s*STG2;
    const uint32_t db = da + A2BYTES;
#pragma unroll
    for (int i=0;i<8;i++){
      int u = tid + i*256;
      int row = u >> 3, cc = u & 7;
      asm volatile("cp.async.cg.shared.global [%0], [%1], 16;"
        :: "r"(da + (uint32_t)(row*144 + cc*16)),
           "l"(A + (size_t)(m0+row)*512 + kk0 + cc*8));
    }
#pragma unroll
    for (int i=0;i<4;i++){
      int u = tid + i*256;
      int row = u >> 3, cc = u & 7;
      asm volatile("cp.async.cg.shared.global [%0], [%1], 16;"
        :: "r"(db + (uint32_t)(row*144 + cc*16)),
           "l"(W + (size_t)(n0+row)*512 + kk0 + cc*8));
    }
    asm volatile("cp.async.commit_group;" ::: "memory");
  }

  __device__ __forceinline__ void compute(int s){
    const uint32_t abase = sbase + s*STG2
        + (uint32_t)((warpM*64 + (lane & 15))*SA*2 + (lane >> 4)*16);
    const uint32_t bbase = sbase + s*STG2 + A2BYTES;
    const int n_off = ((lane >> 4) & 1) * 8 + (lane & 7);
    const int k_off = ((lane >> 3) & 1) * 8;
    uint32_t boff[4];
#pragma unroll
    for (int nip=0; nip<4; nip++)
      boff[nip] = bbase + (uint32_t)(((warpN*64 + nip*16 + n_off)*SA + k_off)*2);
#pragma unroll
    for (int k16=0; k16<4; k16++){
      uint32_t af[4][4];
#pragma unroll
      for (int mf=0; mf<4; mf++)
        ldsm4(af[mf], abase + (uint32_t)(mf*16*SA*2) + k16*32);
      uint32_t bfall[4][4];
#pragma unroll
      for (int nip=0; nip<4; nip++)
        ldsm4(bfall[nip], boff[nip] + k16*32);
#pragma unroll
      for (int mf=0; mf<4; mf++)
#pragma unroll
        for (int nip=0; nip<4; nip++){
          mma16816(acc[mf][2*nip],   af[mf], bfall[nip]);
          mma16816(acc[mf][2*nip+1], af[mf], bfall[nip]+2);
        }
    }
  }

  __device__ __forceinline__ void run(const __half* A, const __half* W){
    load_chunk(0, 0, A, W);
    load_chunk(1, 1, A, W);
    for (int c=0; c<NC; c++){
      if (c < NC-1) asm volatile("cp.async.wait_group 1;" ::: "memory");
      else          asm volatile("cp.async.wait_group 0;" ::: "memory");
      __syncthreads();
      if (c+2 < NC) load_chunk((c+2)%NSTG, c+2, A, W);
      compute(c%NSTG);
    }
  }

  // fp16 output; relu optional
  __device__ __forceinline__ void epilogue(const float* bias, __half* C16, int relu){
    const int g  = lane >> 2;
    const int tg = lane & 3;
#pragma unroll
    for (int mf=0; mf<4; mf++){
      const int row = m0 + warpM*64 + mf*16 + g;
#pragma unroll
      for (int ni=0; ni<8; ni++){
        const int col = n0 + warpN*64 + ni*8 + tg*2;
        const float b0 = bias[col], b1 = bias[col+1];
        float v[4] = {acc[mf][ni][0]+b0, acc[mf][ni][1]+b1,
                      acc[mf][ni][2]+b0, acc[mf][ni][3]+b1};
        if (relu){
#pragma unroll
          for (int e=0;e<4;e++) v[e] = fmaxf(v[e],0.f);
        }
        *reinterpret_cast<__half2*>(&C16[(size_t)row*512+col]) =
            __halves2half2(__float2half(v[0]), __float2half(v[1]));
        *reinterpret_cast<__half2*>(&C16[(size_t)(row+8)*512+col]) =
            __halves2half2(__float2half(v[2]), __float2half(v[3]));
      }
    }
  }
};

__global__ __launch_bounds__(256,1) void gemm_mma(
    const __half* __restrict__ A, const __half* __restrict__ W,
    const float* __restrict__ bias, __half* __restrict__ C16, int relu)
{
  extern __shared__ __align__(16) char smem_raw[];
  GemmCore core;
  core.init(s2u(smem_raw), blockIdx.y*256, blockIdx.x*128);
  core.run(A, W);
  core.epilogue(bias, C16, relu);
}

// Fused QKV: grid (12, 32); weight = blockIdx.x>>2, n-tile = blockIdx.x&3.
struct QKVArgs {
  const __half *w0,*w1,*w2;
  const float *bias0,*bias1,*bias2;
  __half *c0,*c1,*c2;
};

__global__ __launch_bounds__(256,1) void gemm_qkv(
    const __half* __restrict__ A, QKVArgs a)
{
  extern __shared__ __align__(16) char smem_raw[];
  const int w = blockIdx.x >> 2;
  const __half* W    = (w==0) ? a.w0 : (w==1) ? a.w1 : a.w2;
  const float* bias  = (w==0) ? a.bias0 : (w==1) ? a.bias1 : a.bias2;
  __half* C16        = (w==0) ? a.c0 : (w==1) ? a.c1 : a.c2;
  GemmCore core;
  core.init(s2u(smem_raw), blockIdx.y*256, (blockIdx.x & 3)*128);
  core.run(A, W);
  core.epilogue(bias, C16, 0);
}

// ---------------- prep: 5 weight transposes + x fp32->fp16, one launch -----
// blocks [0,1280): weight transpose tiles (5 x 16 x 16); [1280,5376): conv16.
struct PrepArgs {
  const float* w[5];
  __half* t[5];
  const float* x;
  __half* x16;
};

__global__ __launch_bounds__(256) void prep_kernel(PrepArgs a)
{
  const int bx = blockIdx.x;
  if (bx < 1280){
    __shared__ float t[32][33];
    const int wsel = bx >> 8;          // 0..4
    const int tile = bx & 255;         // 16x16 tiles
    const int bxx = (tile & 15) * 32;  // n
    const int byy = (tile >> 4) * 32;  // k
    const float* W = a.w[wsel];
    __half* T      = a.t[wsel];
    const int txx = threadIdx.x & 31, tyy = threadIdx.x >> 5;
#pragma unroll
    for (int i=tyy;i<32;i+=8)
      t[i][txx] = W[(size_t)(byy+i)*512 + bxx + txx];
    __syncthreads();
#pragma unroll
    for (int i=tyy;i<32;i+=8)
      T[(size_t)(bxx+i)*512 + byy + txx] = __float2half(t[txx][i]);
  } else {
    int i = (bx - 1280)*256 + threadIdx.x;   // over float4 quads
    float4 v = reinterpret_cast<const float4*>(a.x)[i];
    reinterpret_cast<__half2*>(a.x16)[2*i]   = __halves2half2(__float2half(v.x), __float2half(v.y));
    reinterpret_cast<__half2*>(a.x16)[2*i+1] = __halves2half2(__float2half(v.z), __float2half(v.w));
  }
}

// ---------------- LayerNorm: one warp per row (no smem, no barriers) -------
__global__ __launch_bounds__(256) void ln_f16(
    const __half* __restrict__ hp, const float* __restrict__ g,
    const float* __restrict__ b, __half* __restrict__ h16)
{
  const int w = threadIdx.x >> 5, lane = threadIdx.x & 31;
  const int row = blockIdx.x*8 + w;
  const __half2* hr = reinterpret_cast<const __half2*>(hp + (size_t)row*512);
  float v0[8], v1[8];
  float s = 0.f;
#pragma unroll
  for (int i=0;i<8;i++){
    __half2 hv = hr[lane + i*32];
    v0[i] = __low2float(hv); v1[i] = __high2float(hv);
    s += v0[i] + v1[i];
  }
#pragma unroll
  for (int o=16;o;o>>=1) s += __shfl_xor_sync(0xffffffffu,s,o);
  const float mu = s * (1.f/512.f);
  float q = 0.f;
#pragma unroll
  for (int i=0;i<8;i++){
    v0[i] -= mu; v1[i] -= mu;
    q += v0[i]*v0[i] + v1[i]*v1[i];
  }
#pragma unroll
  for (int o=16;o;o>>=1) q += __shfl_xor_sync(0xffffffffu,q,o);
  const float rstd = rsqrtf(q * (1.f/512.f) + 1e-5f);
  __half2* orow = reinterpret_cast<__half2*>(h16 + (size_t)row*512);
#pragma unroll
  for (int i=0;i<8;i++){
    const int c = 2*(lane + i*32);
    float o0 = v0[i]*rstd*g[c]   + b[c];
    float o1 = v1[i]*rstd*g[c+1] + b[c+1];
    orow[lane + i*32] = __halves2half2(__float2half(o0), __float2half(o1));
  }
}

// ---------------- Tensor-core flash attention (fp16, no-max softmax) -------
// Per CTA: (b, h, 128 q rows). 256 threads, 8 warps (4 warpM x 2 warpN).
#define QB 144
#define PB 272
#define OQ  0
#define OK0 18432
#define OK1 36864
#define OV  55296
#define OP  73728
#define OLP 108544
#define AT_SMEM (OLP + 1024)

__device__ __forceinline__ void at_load_tile(uint32_t sdst,
    const __half* __restrict__ g, int row0, int col0, int tid)
{
  int row = tid >> 1, half = tid & 1;
  uint32_t d = sdst + (uint32_t)(row*QB + half*64);
  const __half* s = g + (size_t)(row0+row)*512 + col0 + half*32;
#pragma unroll
  for (int j=0;j<4;j++)
    asm volatile("cp.async.cg.shared.global [%0], [%1], 16;" :: "r"(d + j*16), "l"(s + j*8));
}

__global__ __launch_bounds__(256,1) void attn_mma(
    const __half* __restrict__ q16, const __half* __restrict__ k16,
    const __half* __restrict__ v16,
    const float* __restrict__ adj, const int* __restrict__ use_adj,
    __half* __restrict__ c16)
{
  extern __shared__ __align__(16) char sm8[];
  const uint32_t sb = s2u(sm8);
  float* lp = reinterpret_cast<float*>(sm8 + OLP);

  const int tid = threadIdx.x, lane = tid & 31, wid = tid >> 5;
  const int warpM = wid >> 1, warpN = wid & 1;
  const int q0 = blockIdx.x * 128;
  const int hh = blockIdx.y, bb = blockIdx.z;
  const int ua = use_adj[0];
  const int col0 = hh * 64;
  const int rowg0 = bb * 512;

  at_load_tile(sb+OQ, q16, rowg0+q0, col0, tid);
  lp[tid] = 0.f;

  float oacc[2][4][4];
#pragma unroll
  for (int i=0;i<2;i++)
#pragma unroll
    for (int j=0;j<4;j++)
#pragma unroll
      for (int e=0;e<4;e++) oacc[i][j][e]=0.f;

  const uint32_t a_off  = (uint32_t)((lane&15)*QB + (lane>>4)*16);
  const uint32_t b_off  = (uint32_t)((((lane>>4)&1)*8 + (lane&7))*QB + ((lane>>3)&1)*16);
  const uint32_t ap_off = (uint32_t)((lane&15)*PB + (lane>>4)*16);

  const int r0 = warpM*32 + (lane>>2);
  const int cb = warpN*64 + 2*(lane&3);

  for (int kb=0; kb<4; kb++){
    const int krow0 = rowg0 + kb*128;
    if (kb == 0){
      at_load_tile(sb+OK0, k16, krow0, col0, tid);
      at_load_tile(sb+OV,  v16, krow0, col0, tid);
      asm volatile("cp.async.commit_group;" ::: "memory");
      asm volatile("cp.async.wait_group 0;" ::: "memory");
      __syncthreads();
    }

    // ---- S = Q K^T ----
    float sacc[2][8][4];
#pragma unroll
    for (int i=0;i<2;i++)
#pragma unroll
      for (int j=0;j<8;j++)
#pragma unroll
        for (int e=0;e<4;e++) sacc[i][j][e]=0.f;

    {
      const uint32_t qb_ = sb + OQ + (uint32_t)(warpM*32*QB) + a_off;
      const uint32_t kb_ = sb + ((kb&1) ? OK1 : OK0) + (uint32_t)(warpN*64*QB) + b_off;
#pragma unroll
      for (int k16i=0;k16i<4;k16i++){
        uint32_t af[2][4];
        ldsm4(af[0], qb_ + k16i*32);
        ldsm4(af[1], qb_ + 16*QB + k16i*32);
#pragma unroll
        for (int nf=0;nf<4;nf++){
          uint32_t bf[4];
          ldsm4(bf, kb_ + (uint32_t)(nf*16*QB) + k16i*32);
          mma16816(sacc[0][2*nf],   af[0], bf);
          mma16816(sacc[0][2*nf+1], af[0], bf+2);
          mma16816(sacc[1][2*nf],   af[1], bf);
          mma16816(sacc[1][2*nf+1], af[1], bf+2);
        }
      }
    }

    // ---- scale*adj, exp, row sums, store P fp16 ----
#pragma unroll
    for (int mi=0;mi<2;mi++){
      const int rr = r0 + mi*16;
      float rs0 = 0.f, rs8 = 0.f;
#pragma unroll
      for (int nf=0;nf<8;nf++){
        const int cc = cb + nf*8;
        float m0=1.f,m1=1.f,m2=1.f,m3=1.f;
        if (ua){
          const float* ar = adj + ((size_t)(rowg0+q0+rr))*512 + kb*128 + cc;
          float2 a01 = *reinterpret_cast<const float2*>(ar);
          float2 a23 = *reinterpret_cast<const float2*>(ar + 8*512);
          m0=a01.x; m1=a01.y; m2=a23.x; m3=a23.y;
        }
        float p0 = fexp(sacc[mi][nf][0]*0.125f*m0);
        float p1 = fexp(sacc[mi][nf][1]*0.125f*m1);
        float p2 = fexp(sacc[mi][nf][2]*0.125f*m2);
        float p3 = fexp(sacc[mi][nf][3]*0.125f*m3);
        rs0 += p0+p1;  rs8 += p2+p3;
        __half2 t0 = __halves2half2(__float2half(p0), __float2half(p1));
        __half2 t1 = __halves2half2(__float2half(p2), __float2half(p3));
        uint32_t ph01 = *reinterpret_cast<uint32_t*>(&t0);
        uint32_t ph23 = *reinterpret_cast<uint32_t*>(&t1);
        uint32_t pa = sb + OP + (uint32_t)(rr*PB + cc*2);
        asm volatile("st.shared.b32 [%0], %1;" :: "r"(pa), "r"(ph01));
        asm volatile("st.shared.b32 [%0], %1;" :: "r"(pa + 8*PB), "r"(ph23));
      }
      rs0 += __shfl_xor_sync(0xffffffffu, rs0, 1);
      rs0 += __shfl_xor_sync(0xffffffffu, rs0, 2);
      rs8 += __shfl_xor_sync(0xffffffffu, rs8, 1);
      rs8 += __shfl_xor_sync(0xffffffffu, rs8, 2);
      if ((lane&3)==0){
        lp[warpN*128 + rr]     += rs0;
        lp[warpN*128 + rr + 8] += rs8;
      }
    }
    __syncthreads();   // P visible; K[kb&1] free

    if (kb < 3){       // prefetch next K into other buffer while PV runs
      at_load_tile(sb + ((kb&1) ? OK0 : OK1), k16, krow0+128, col0, tid);
      asm volatile("cp.async.commit_group;" ::: "memory");
    }

    // ---- O += P V, V^T via ldmatrix.trans ----
    {
      const uint32_t pb2 = sb + OP + (uint32_t)(warpM*32*PB) + ap_off;
      const uint32_t vb2 = sb + OV + (uint32_t)((lane&15)*QB + (warpN*32 + (lane>>4)*8)*2);
#pragma unroll
      for (int k16i=0;k16i<8;k16i++){
        uint32_t af[2][4];
        ldsm4(af[0], pb2 + k16i*32);
        ldsm4(af[1], pb2 + 16*PB + k16i*32);
#pragma unroll
        for (int nf=0;nf<2;nf++){
          uint32_t bf[4];
          ldsm4t(bf, vb2 + (uint32_t)(k16i*16*QB) + (uint32_t)(nf*16*2));
          mma16816(oacc[0][2*nf],   af[0], bf);
          mma16816(oacc[0][2*nf+1], af[0], bf+2);
          mma16816(oacc[1][2*nf],   af[1], bf);
          mma16816(oacc[1][2*nf+1], af[1], bf+2);
        }
      }
    }
    __syncthreads();   // V reads complete

    if (kb < 3){
      at_load_tile(sb+OV, v16, krow0+128, col0, tid);
      asm volatile("cp.async.commit_group;" ::: "memory");
      asm volatile("cp.async.wait_group 0;" ::: "memory");
      __syncthreads();
    }
  }

  // ---- epilogue: normalize, store fp16 ctx ----
  if (tid < 128) lp[tid] = 1.f / (lp[tid] + lp[128 + tid]);
  __syncthreads();
#pragma unroll
  for (int mi=0;mi<2;mi++){
    const int rr = r0 + mi*16;
    const float inv0 = lp[rr], inv8 = lp[rr+8];
    const size_t rga = (size_t)(rowg0 + q0 + rr);
#pragma unroll
    for (int nf=0;nf<4;nf++){
      const int colg = col0 + warpN*32 + nf*8 + 2*(lane&3);
      *reinterpret_cast<__half2*>(&c16[rga*512 + colg]) =
          __halves2half2(__float2half(oacc[mi][nf][0]*inv0),
                         __float2half(oacc[mi][nf][1]*inv0));
      *reinterpret_cast<__half2*>(&c16[(rga+8)*512 + colg]) =
          __halves2half2(__float2half(oacc[mi][nf][2]*inv8),
                         __float2half(oacc[mi][nf][3]*inv8));
    }
  }
}

// ---------------- Gate + blend: out = c*x + (1-c)*h2 (h2 fp16) -------------
__global__ void gate_kernel(const float* __restrict__ x, const __half* __restrict__ h2,
    const float* __restrict__ gw, const float* __restrict__ gb, float* __restrict__ out)
{
  const int w = threadIdx.x>>5, lane = threadIdx.x&31;
  const int row = blockIdx.x*8 + w;
  const float* xr = x  + (size_t)row*512;
  const __half* hr = h2 + (size_t)row*512;
  float hf[16];
  float s = 0.f;
#pragma unroll
  for (int i=0;i<16;i++){
    int c = i*32 + lane;
    hf[i] = __half2float(hr[c]);
    s += xr[c]*gw[c] + hf[i]*gw[512+c];
  }
#pragma unroll
  for (int off=16;off;off>>=1) s += __shfl_xor_sync(0xffffffffu,s,off);
  s += gb[0];
  float coeff = 1.f/(1.f+__expf(-s));
  float* orow = out + (size_t)row*512;
#pragma unroll
  for (int i=0;i<16;i++){
    int c = i*32+lane;
    orow[c] = coeff*xr[c] + (1.f-coeff)*hf[i];
  }
}

// ---------------- launch ---------------------------------------------------
extern "C" void kernel_launch(void* const* d_in, const int* in_sizes, int n_in,
                              void* d_out, int out_size)
{
  const float* x   = (const float*)d_in[0];
  const float* adj = (const float*)d_in[1];
  const float* W_w = (const float*)d_in[2];
  const float* W_b = (const float*)d_in[3];
  const float* lng = (const float*)d_in[4];
  const float* lnb = (const float*)d_in[5];
  const float* Wq  = (const float*)d_in[6];
  const float* bq  = (const float*)d_in[7];
  const float* Wk  = (const float*)d_in[8];
  const float* bk  = (const float*)d_in[9];
  const float* Wv  = (const float*)d_in[10];
  const float* bv  = (const float*)d_in[11];
  const float* Wo  = (const float*)d_in[12];
  const float* bo  = (const float*)d_in[13];
  const float* gw  = (const float*)d_in[14];
  const float* gbb = (const float*)d_in[15];
  const int*   ua  = (const int*)d_in[16];
  float* out = (float*)d_out;

  __half *x16,*hp16,*h16,*q16,*k16,*v16,*c16,*h2_16,*ww,*wq,*wk,*wv,*wo;
  cudaGetSymbolAddress((void**)&x16,  g_x16);
  cudaGetSymbolAddress((void**)&hp16, g_hp16);
  cudaGetSymbolAddress((void**)&h16,  g_h16);
  cudaGetSymbolAddress((void**)&q16,  g_q16);
  cudaGetSymbolAddress((void**)&k16,  g_k16);
  cudaGetSymbolAddress((void**)&v16,  g_v16);
  cudaGetSymbolAddress((void**)&c16,  g_c16);
  cudaGetSymbolAddress((void**)&h2_16,g_h2_16);
  cudaGetSymbolAddress((void**)&ww,   g_ww);
  cudaGetSymbolAddress((void**)&wq,   g_wq);
  cudaGetSymbolAddress((void**)&wk,   g_wk);
  cudaGetSymbolAddress((void**)&wv,   g_wv);
  cudaGetSymbolAddress((void**)&wo,   g_wo);

  cudaFuncSetAttribute(gemm_mma, cudaFuncAttributeMaxDynamicSharedMemorySize, GEMM_SMEM);
  cudaFuncSetAttribute(gemm_qkv, cudaFuncAttributeMaxDynamicSharedMemorySize, GEMM_SMEM);
  cudaFuncSetAttribute(attn_mma, cudaFuncAttributeMaxDynamicSharedMemorySize, AT_SMEM);

  QKVArgs qa;
  qa.w0=wq; qa.w1=wk; qa.w2=wv;
  qa.bias0=bq; qa.bias1=bk; qa.bias2=bv;
  qa.c0=q16; qa.c1=k16; qa.c2=v16;

  PrepArgs pa;
  pa.w[0]=W_w; pa.w[1]=Wq; pa.w[2]=Wk; pa.w[3]=Wv; pa.w[4]=Wo;
  pa.t[0]=ww; pa.t[1]=wq; pa.t[2]=wk; pa.t[3]=wv; pa.t[4]=wo;
  pa.x = x; pa.x16 = x16;

  prep_kernel<<<5376,256>>>(pa);
  gemm_mma<<<dim3(4,32),256,GEMM_SMEM>>>(x16, ww, W_b, hp16, 0);
  ln_f16<<<1024,256>>>(hp16, lng, lnb, h16);
  gemm_qkv<<<dim3(12,32),256,GEMM_SMEM>>>(h16, qa);
  attn_mma<<<dim3(4,8,16),256,AT_SMEM>>>(q16,k16,v16,adj,ua,c16);
  gemm_mma<<<dim3(4,32),256,GEMM_SMEM>>>(c16, wo, bo, h2_16, 1);
  gate_kernel<<<1024,256>>>(x, h2_16, gw, gbb, out);
}

// round 13
// speedup vs baseline: 1.0154x; 1.0154x over previous
#include <cuda_runtime.h>
#include <cuda_fp16.h>
#include <cstdint>

// Problem constants
#define MROWS 8192
#define DM 512

// ---------------- scratch (static device arrays; no cudaMalloc allowed) ----
static __device__ __half g_x16[MROWS*DM];
static __device__ __half g_hp16[MROWS*DM];   // pre-LN h (fp16)
static __device__ __half g_h16[MROWS*DM];    // post-LN h (fp16)
static __device__ __half g_q16[MROWS*DM], g_k16[MROWS*DM], g_v16[MROWS*DM];
static __device__ __half g_c16[MROWS*DM];    // attention ctx
static __device__ __half g_h2_16[MROWS*DM];  // relu(ctx@Wo+bo)
// fp16 transposed weights ([n,k] so D = A·B^T = A·W)
static __device__ __half g_ww[DM*DM], g_wq[DM*DM], g_wk[DM*DM], g_wv[DM*DM], g_wo[DM*DM];

__device__ __forceinline__ uint32_t s2u(const void* p){
  return (uint32_t)__cvta_generic_to_shared(p);
}

// ---------------- mma.sync helpers -----------------------------------------
__device__ __forceinline__ void ldsm4(uint32_t* r, uint32_t addr){
  asm volatile("ldmatrix.sync.aligned.m8n8.x4.shared.b16 {%0,%1,%2,%3}, [%4];"
   : "=r"(r[0]),"=r"(r[1]),"=r"(r[2]),"=r"(r[3]) : "r"(addr));
}
__device__ __forceinline__ void ldsm4t(uint32_t* r, uint32_t addr){
  asm volatile("ldmatrix.sync.aligned.m8n8.x4.trans.shared.b16 {%0,%1,%2,%3}, [%4];"
   : "=r"(r[0]),"=r"(r[1]),"=r"(r[2]),"=r"(r[3]) : "r"(addr));
}
__device__ __forceinline__ void mma16816(float* d, const uint32_t* a, const uint32_t* b){
  asm volatile("mma.sync.aligned.m16n8k16.row.col.f32.f16.f16.f32 "
    "{%0,%1,%2,%3}, {%4,%5,%6,%7}, {%8,%9}, {%0,%1,%2,%3};"
    : "+f"(d[0]),"+f"(d[1]),"+f"(d[2]),"+f"(d[3])
    : "r"(a[0]),"r"(a[1]),"r"(a[2]),"r"(a[3]), "r"(b[0]),"r"(b[1]));
}

// fast exp: fp32 accuracy ~2.4e-6, runs on fma/alu pipes (no MUFU)
__device__ __forceinline__ float fexp(float x){
  float y = x * 1.44269504f;
  int   ki = __float2int_rn(y);
  float f  = y - (float)ki;
  float p = 1.333355815e-3f;
  p = fmaf(p, f, 9.618129107e-3f);
  p = fmaf(p, f, 5.550410866e-2f);
  p = fmaf(p, f, 2.402265069e-1f);
  p = fmaf(p, f, 6.931471806e-1f);
  p = fmaf(p, f, 1.0f);
  return p * __int_as_float((ki + 127) << 23);
}

// ---------------- GEMM core: CTA 256x128, 16 warps (4x4), warp tile 64x32 --
// C16[8192,512] = A @ W^T(+bias). BK=64, 512 threads, 3-stage cp.async ring.
#define SA 72
#define A2BYTES (256*SA*2)           // 36864
#define B2BYTES (128*SA*2)           // 18432
#define STG2 (A2BYTES + B2BYTES)     // 55296
#define NSTG 3
#define GEMM_SMEM (NSTG*STG2)        // 165888
#define NC 8

struct GemmCore {
  uint32_t sbase;
  int m0, n0, tid, lane, warpM, warpN;
  float acc[4][4][4];

  __device__ __forceinline__ void init(uint32_t sb, int m0_, int n0_){
    sbase = sb; m0 = m0_; n0 = n0_;
    tid = threadIdx.x; lane = tid & 31;
    int wid = tid >> 5; warpM = wid >> 2; warpN = wid & 3;
#pragma unroll
    for (int i=0;i<4;i++)
#pragma unroll
      for (int j=0;j<4;j++)
#pragma unroll
        for (int r=0;r<4;r++) acc[i][j][r]=0.f;
  }

  __device__ __forceinline__ void load_chunk(int s, int c,
      const __half* A, const __half* W){
    const int kk0 = c * 64;
    const uint32_t da = sbase + s*STG2;
    const uint32_t db = da + A2BYTES;
    // A: 256 rows x 64 halves = 2048 16B units, 4 per thread
#pragma unroll
    for (int i=0;i<4;i++){
      int u = tid + i*512;
      int row = u >> 3, cc = u & 7;
      asm volatile("cp.async.cg.shared.global [%0], [%1], 16;"
        :: "r"(da + (uint32_t)(row*144 + cc*16)),
           "l"(A + (size_t)(m0+row)*512 + kk0 + cc*8));
    }
    // B: 128 rows x 64 halves = 1024 units, 2 per thread
#pragma unroll
    for (int i=0;i<2;i++){
      int u = tid + i*512;
      int row = u >> 3, cc = u & 7;
      asm volatile("cp.async.cg.shared.global [%0], [%1], 16;"
        :: "r"(db + (uint32_t)(row*144 + cc*16)),
           "l"(W + (size_t)(n0+row)*512 + kk0 + cc*8));
    }
    asm volatile("cp.async.commit_group;" ::: "memory");
  }

  __device__ __forceinline__ void compute(int s){
    const uint32_t abase = sbase + s*STG2
        + (uint32_t)((warpM*64 + (lane & 15))*SA*2 + (lane >> 4)*16);
    const uint32_t bbase = sbase + s*STG2 + A2BYTES;
    const int n_off = ((lane >> 4) & 1) * 8 + (lane & 7);
    const int k_off = ((lane >> 3) & 1) * 8;
    uint32_t boff[2];
#pragma unroll
    for (int nip=0; nip<2; nip++)
      boff[nip] = bbase + (uint32_t)(((warpN*32 + nip*16 + n_off)*SA + k_off)*2);
#pragma unroll
    for (int k16=0; k16<4; k16++){
      uint32_t af[4][4];
#pragma unroll
      for (int mf=0; mf<4; mf++)
        ldsm4(af[mf], abase + (uint32_t)(mf*16*SA*2) + k16*32);
      uint32_t bf[2][4];
#pragma unroll
      for (int nip=0; nip<2; nip++)
        ldsm4(bf[nip], boff[nip] + k16*32);
#pragma unroll
      for (int mf=0; mf<4; mf++)
#pragma unroll
        for (int nip=0; nip<2; nip++){
          mma16816(acc[mf][2*nip],   af[mf], bf[nip]);
          mma16816(acc[mf][2*nip+1], af[mf], bf[nip]+2);
        }
    }
  }

  __device__ __forceinline__ void run(const __half* A, const __half* W){
    load_chunk(0, 0, A, W);
    load_chunk(1, 1, A, W);
    for (int c=0; c<NC; c++){
      if (c < NC-1) asm volatile("cp.async.wait_group 1;" ::: "memory");
      else          asm volatile("cp.async.wait_group 0;" ::: "memory");
      __syncthreads();
      if (c+2 < NC) load_chunk((c+2)%NSTG, c+2, A, W);
      compute(c%NSTG);
    }
  }

  // fp16 output; relu optional
  __device__ __forceinline__ void epilogue(const float* bias, __half* C16, int relu){
    const int g  = lane >> 2;
    const int tg = lane & 3;
#pragma unroll
    for (int mf=0; mf<4; mf++){
      const int row = m0 + warpM*64 + mf*16 + g;
#pragma unroll
      for (int ni=0; ni<4; ni++){
        const int col = n0 + warpN*32 + ni*8 + tg*2;
        const float b0 = bias[col], b1 = bias[col+1];
        float v[4] = {acc[mf][ni][0]+b0, acc[mf][ni][1]+b1,
                      acc[mf][ni][2]+b0, acc[mf][ni][3]+b1};
        if (relu){
#pragma unroll
          for (int e=0;e<4;e++) v[e] = fmaxf(v[e],0.f);
        }
        *reinterpret_cast<__half2*>(&C16[(size_t)row*512+col]) =
            __halves2half2(__float2half(v[0]), __float2half(v[1]));
        *reinterpret_cast<__half2*>(&C16[(size_t)(row+8)*512+col]) =
            __halves2half2(__float2half(v[2]), __float2half(v[3]));
      }
    }
  }
};

__global__ __launch_bounds__(512,1) void gemm_mma(
    const __half* __restrict__ A, const __half* __restrict__ W,
    const float* __restrict__ bias, __half* __restrict__ C16, int relu)
{
  extern __shared__ __align__(16) char smem_raw[];
  GemmCore core;
  core.init(s2u(smem_raw), blockIdx.y*256, blockIdx.x*128);
  core.run(A, W);
  core.epilogue(bias, C16, relu);
}

// Fused QKV: grid (12, 32); weight = blockIdx.x>>2, n-tile = blockIdx.x&3.
struct QKVArgs {
  const __half *w0,*w1,*w2;
  const float *bias0,*bias1,*bias2;
  __half *c0,*c1,*c2;
};

__global__ __launch_bounds__(512,1) void gemm_qkv(
    const __half* __restrict__ A, QKVArgs a)
{
  extern __shared__ __align__(16) char smem_raw[];
  const int w = blockIdx.x >> 2;
  const __half* W    = (w==0) ? a.w0 : (w==1) ? a.w1 : a.w2;
  const float* bias  = (w==0) ? a.bias0 : (w==1) ? a.bias1 : a.bias2;
  __half* C16        = (w==0) ? a.c0 : (w==1) ? a.c1 : a.c2;
  GemmCore core;
  core.init(s2u(smem_raw), blockIdx.y*256, (blockIdx.x & 3)*128);
  core.run(A, W);
  core.epilogue(bias, C16, 0);
}

// ---------------- prep: 5 weight transposes + x fp32->fp16, one launch -----
struct PrepArgs {
  const float* w[5];
  __half* t[5];
  const float* x;
  __half* x16;
};

__global__ __launch_bounds__(256) void prep_kernel(PrepArgs a)
{
  const int bx = blockIdx.x;
  if (bx < 1280){
    __shared__ float t[32][33];
    const int wsel = bx >> 8;          // 0..4
    const int tile = bx & 255;         // 16x16 tiles
    const int bxx = (tile & 15) * 32;  // n
    const int byy = (tile >> 4) * 32;  // k
    const float* W = a.w[wsel];
    __half* T      = a.t[wsel];
    const int txx = threadIdx.x & 31, tyy = threadIdx.x >> 5;
#pragma unroll
    for (int i=tyy;i<32;i+=8)
      t[i][txx] = W[(size_t)(byy+i)*512 + bxx + txx];
    __syncthreads();
#pragma unroll
    for (int i=tyy;i<32;i+=8)
      T[(size_t)(bxx+i)*512 + byy + txx] = __float2half(t[txx][i]);
  } else {
    int i = (bx - 1280)*256 + threadIdx.x;   // over float4 quads
    float4 v = reinterpret_cast<const float4*>(a.x)[i];
    reinterpret_cast<__half2*>(a.x16)[2*i]   = __halves2half2(__float2half(v.x), __float2half(v.y));
    reinterpret_cast<__half2*>(a.x16)[2*i+1] = __halves2half2(__float2half(v.z), __float2half(v.w));
  }
}

// ---------------- LayerNorm: one warp per row (no smem, no barriers) -------
__global__ __launch_bounds__(256) void ln_f16(
    const __half* __restrict__ hp, const float* __restrict__ g,
    const float* __restrict__ b, __half* __restrict__ h16)
{
  const int w = threadIdx.x >> 5, lane = threadIdx.x & 31;
  const int row = blockIdx.x*8 + w;
  const __half2* hr = reinterpret_cast<const __half2*>(hp + (size_t)row*512);
  float v0[8], v1[8];
  float s = 0.f;
#pragma unroll
  for (int i=0;i<8;i++){
    __half2 hv = hr[lane + i*32];
    v0[i] = __low2float(hv); v1[i] = __high2float(hv);
    s += v0[i] + v1[i];
  }
#pragma unroll
  for (int o=16;o;o>>=1) s += __shfl_xor_sync(0xffffffffu,s,o);
  const float mu = s * (1.f/512.f);
  float q = 0.f;
#pragma unroll
  for (int i=0;i<8;i++){
    v0[i] -= mu; v1[i] -= mu;
    q += v0[i]*v0[i] + v1[i]*v1[i];
  }
#pragma unroll
  for (int o=16;o;o>>=1) q += __shfl_xor_sync(0xffffffffu,q,o);
  const float rstd = rsqrtf(q * (1.f/512.f) + 1e-5f);
  __half2* orow = reinterpret_cast<__half2*>(h16 + (size_t)row*512);
#pragma unroll
  for (int i=0;i<8;i++){
    const int c = 2*(lane + i*32);
    float o0 = v0[i]*rstd*g[c]   + b[c];
    float o1 = v1[i]*rstd*g[c+1] + b[c+1];
    orow[lane + i*32] = __halves2half2(__float2half(o0), __float2half(o1));
  }
}

// ---------------- Tensor-core flash attention (fp16, no-max softmax) -------
// Per CTA: (b, h, 128 q rows). 256 threads, 8 warps (4 warpM x 2 warpN).
#define QB 144
#define PB 272
#define OQ  0
#define OK0 18432
#define OK1 36864
#define OV  55296
#define OP  73728
#define OLP 108544
#define AT_SMEM (OLP + 1024)

__device__ __forceinline__ void at_load_tile(uint32_t sdst,
    const __half* __restrict__ g, int row0, int col0, int tid)
{
  int row = tid >> 1, half = tid & 1;
  uint32_t d = sdst + (uint32_t)(row*QB + half*64);
  const __half* s = g + (size_t)(row0+row)*512 + col0 + half*32;
#pragma unroll
  for (int j=0;j<4;j++)
    asm volatile("cp.async.cg.shared.global [%0], [%1], 16;" :: "r"(d + j*16), "l"(s + j*8));
}

__global__ __launch_bounds__(256,1) void attn_mma(
    const __half* __restrict__ q16, const __half* __restrict__ k16,
    const __half* __restrict__ v16,
    const float* __restrict__ adj, const int* __restrict__ use_adj,
    __half* __restrict__ c16)
{
  extern __shared__ __align__(16) char sm8[];
  const uint32_t sb = s2u(sm8);
  float* lp = reinterpret_cast<float*>(sm8 + OLP);

  const int tid = threadIdx.x, lane = tid & 31, wid = tid >> 5;
  const int warpM = wid >> 1, warpN = wid & 1;
  const int q0 = blockIdx.x * 128;
  const int hh = blockIdx.y, bb = blockIdx.z;
  const int ua = use_adj[0];
  const int col0 = hh * 64;
  const int rowg0 = bb * 512;

  at_load_tile(sb+OQ, q16, rowg0+q0, col0, tid);
  lp[tid] = 0.f;

  float oacc[2][4][4];
#pragma unroll
  for (int i=0;i<2;i++)
#pragma unroll
    for (int j=0;j<4;j++)
#pragma unroll
      for (int e=0;e<4;e++) oacc[i][j][e]=0.f;

  const uint32_t a_off  = (uint32_t)((lane&15)*QB + (lane>>4)*16);
  const uint32_t b_off  = (uint32_t)((((lane>>4)&1)*8 + (lane&7))*QB + ((lane>>3)&1)*16);
  const uint32_t ap_off = (uint32_t)((lane&15)*PB + (lane>>4)*16);

  const int r0 = warpM*32 + (lane>>2);
  const int cb = warpN*64 + 2*(lane&3);

  for (int kb=0; kb<4; kb++){
    const int krow0 = rowg0 + kb*128;
    if (kb == 0){
      at_load_tile(sb+OK0, k16, krow0, col0, tid);
      at_load_tile(sb+OV,  v16, krow0, col0, tid);
      asm volatile("cp.async.commit_group;" ::: "memory");
      asm volatile("cp.async.wait_group 0;" ::: "memory");
      __syncthreads();
    }

    // ---- S = Q K^T ----
    float sacc[2][8][4];
#pragma unroll
    for (int i=0;i<2;i++)
#pragma unroll
      for (int j=0;j<8;j++)
#pragma unroll
        for (int e=0;e<4;e++) sacc[i][j][e]=0.f;

    {
      const uint32_t qb_ = sb + OQ + (uint32_t)(warpM*32*QB) + a_off;
      const uint32_t kb_ = sb + ((kb&1) ? OK1 : OK0) + (uint32_t)(warpN*64*QB) + b_off;
#pragma unroll
      for (int k16i=0;k16i<4;k16i++){
        uint32_t af[2][4];
        ldsm4(af[0], qb_ + k16i*32);
        ldsm4(af[1], qb_ + 16*QB + k16i*32);
#pragma unroll
        for (int nf=0;nf<4;nf++){
          uint32_t bf[4];
          ldsm4(bf, kb_ + (uint32_t)(nf*16*QB) + k16i*32);
          mma16816(sacc[0][2*nf],   af[0], bf);
          mma16816(sacc[0][2*nf+1], af[0], bf+2);
          mma16816(sacc[1][2*nf],   af[1], bf);
          mma16816(sacc[1][2*nf+1], af[1], bf+2);
        }
      }
    }

    // ---- scale*adj, exp, row sums, store P fp16 ----
#pragma unroll
    for (int mi=0;mi<2;mi++){
      const int rr = r0 + mi*16;
      float rs0 = 0.f, rs8 = 0.f;
#pragma unroll
      for (int nf=0;nf<8;nf++){
        const int cc = cb + nf*8;
        float m0=1.f,m1=1.f,m2=1.f,m3=1.f;
        if (ua){
          const float* ar = adj + ((size_t)(rowg0+q0+rr))*512 + kb*128 + cc;
          float2 a01 = *reinterpret_cast<const float2*>(ar);
          float2 a23 = *reinterpret_cast<const float2*>(ar + 8*512);
          m0=a01.x; m1=a01.y; m2=a23.x; m3=a23.y;
        }
        float p0 = fexp(sacc[mi][nf][0]*0.125f*m0);
        float p1 = fexp(sacc[mi][nf][1]*0.125f*m1);
        float p2 = fexp(sacc[mi][nf][2]*0.125f*m2);
        float p3 = fexp(sacc[mi][nf][3]*0.125f*m3);
        rs0 += p0+p1;  rs8 += p2+p3;
        __half2 t0 = __halves2half2(__float2half(p0), __float2half(p1));
        __half2 t1 = __halves2half2(__float2half(p2), __float2half(p3));
        uint32_t ph01 = *reinterpret_cast<uint32_t*>(&t0);
        uint32_t ph23 = *reinterpret_cast<uint32_t*>(&t1);
        uint32_t pa = sb + OP + (uint32_t)(rr*PB + cc*2);
        asm volatile("st.shared.b32 [%0], %1;" :: "r"(pa), "r"(ph01));
        asm volatile("st.shared.b32 [%0], %1;" :: "r"(pa + 8*PB), "r"(ph23));
      }
      rs0 += __shfl_xor_sync(0xffffffffu, rs0, 1);
      rs0 += __shfl_xor_sync(0xffffffffu, rs0, 2);
      rs8 += __shfl_xor_sync(0xffffffffu, rs8, 1);
      rs8 += __shfl_xor_sync(0xffffffffu, rs8, 2);
      if ((lane&3)==0){
        lp[warpN*128 + rr]     += rs0;
        lp[warpN*128 + rr + 8] += rs8;
      }
    }
    __syncthreads();   // P visible; K[kb&1] free

    if (kb < 3){       // prefetch next K into other buffer while PV runs
      at_load_tile(sb + ((kb&1) ? OK0 : OK1), k16, krow0+128, col0, tid);
      asm volatile("cp.async.commit_group;" ::: "memory");
    }

    // ---- O += P V, V^T via ldmatrix.trans ----
    {
      const uint32_t pb2 = sb + OP + (uint32_t)(warpM*32*PB) + ap_off;
      const uint32_t vb2 = sb + OV + (uint32_t)((lane&15)*QB + (warpN*32 + (lane>>4)*8)*2);
#pragma unroll
      for (int k16i=0;k16i<8;k16i++){
        uint32_t af[2][4];
        ldsm4(af[0], pb2 + k16i*32);
        ldsm4(af[1], pb2 + 16*PB + k16i*32);
#pragma unroll
        for (int nf=0;nf<2;nf++){
          uint32_t bf[4];
          ldsm4t(bf, vb2 + (uint32_t)(k16i*16*QB) + (uint32_t)(nf*16*2));
          mma16816(oacc[0][2*nf],   af[0], bf);
          mma16816(oacc[0][2*nf+1], af[0], bf+2);
          mma16816(oacc[1][2*nf],   af[1], bf);
          mma16816(oacc[1][2*nf+1], af[1], bf+2);
        }
      }
    }
    __syncthreads();   // V reads complete

    if (kb < 3){
      at_load_tile(sb+OV, v16, krow0+128, col0, tid);
      asm volatile("cp.async.commit_group;" ::: "memory");
      asm volatile("cp.async.wait_group 0;" ::: "memory");
      __syncthreads();
    }
  }

  // ---- epilogue: normalize, store fp16 ctx ----
  if (tid < 128) lp[tid] = 1.f / (lp[tid] + lp[128 + tid]);
  __syncthreads();
#pragma unroll
  for (int mi=0;mi<2;mi++){
    const int rr = r0 + mi*16;
    const float inv0 = lp[rr], inv8 = lp[rr+8];
    const size_t rga = (size_t)(rowg0 + q0 + rr);
#pragma unroll
    for (int nf=0;nf<4;nf++){
      const int colg = col0 + warpN*32 + nf*8 + 2*(lane&3);
      *reinterpret_cast<__half2*>(&c16[rga*512 + colg]) =
          __halves2half2(__float2half(oacc[mi][nf][0]*inv0),
                         __float2half(oacc[mi][nf][1]*inv0));
      *reinterpret_cast<__half2*>(&c16[(rga+8)*512 + colg]) =
          __halves2half2(__float2half(oacc[mi][nf][2]*inv8),
                         __float2half(oacc[mi][nf][3]*inv8));
    }
  }
}

// ---------------- Gate + blend: out = c*x + (1-c)*h2 (h2 fp16) -------------
__global__ void gate_kernel(const float* __restrict__ x, const __half* __restrict__ h2,
    const float* __restrict__ gw, const float* __restrict__ gb, float* __restrict__ out)
{
  const int w = threadIdx.x>>5, lane = threadIdx.x&31;
  const int row = blockIdx.x*8 + w;
  const float* xr = x  + (size_t)row*512;
  const __half* hr = h2 + (size_t)row*512;
  float hf[16];
  float s = 0.f;
#pragma unroll
  for (int i=0;i<16;i++){
    int c = i*32 + lane;
    hf[i] = __half2float(hr[c]);
    s += xr[c]*gw[c] + hf[i]*gw[512+c];
  }
#pragma unroll
  for (int off=16;off;off>>=1) s += __shfl_xor_sync(0xffffffffu,s,off);
  s += gb[0];
  float coeff = 1.f/(1.f+__expf(-s));
  float* orow = out + (size_t)row*512;
#pragma unroll
  for (int i=0;i<16;i++){
    int c = i*32+lane;
    orow[c] = coeff*xr[c] + (1.f-coeff)*hf[i];
  }
}

// ---------------- launch ---------------------------------------------------
extern "C" void kernel_launch(void* const* d_in, const int* in_sizes, int n_in,
                              void* d_out, int out_size)
{
  const float* x   = (const float*)d_in[0];
  const float* adj = (const float*)d_in[1];
  const float* W_w = (const float*)d_in[2];
  const float* W_b = (const float*)d_in[3];
  const float* lng = (const float*)d_in[4];
  const float* lnb = (const float*)d_in[5];
  const float* Wq  = (const float*)d_in[6];
  const float* bq  = (const float*)d_in[7];
  const float* Wk  = (const float*)d_in[8];
  const float* bk  = (const float*)d_in[9];
  const float* Wv  = (const float*)d_in[10];
  const float* bv  = (const float*)d_in[11];
  const float* Wo  = (const float*)d_in[12];
  const float* bo  = (const float*)d_in[13];
  const float* gw  = (const float*)d_in[14];
  const float* gbb = (const float*)d_in[15];
  const int*   ua  = (const int*)d_in[16];
  float* out = (float*)d_out;

  __half *x16,*hp16,*h16,*q16,*k16,*v16,*c16,*h2_16,*ww,*wq,*wk,*wv,*wo;
  cudaGetSymbolAddress((void**)&x16,  g_x16);
  cudaGetSymbolAddress((void**)&hp16, g_hp16);
  cudaGetSymbolAddress((void**)&h16,  g_h16);
  cudaGetSymbolAddress((void**)&q16,  g_q16);
  cudaGetSymbolAddress((void**)&k16,  g_k16);
  cudaGetSymbolAddress((void**)&v16,  g_v16);
  cudaGetSymbolAddress((void**)&c16,  g_c16);
  cudaGetSymbolAddress((void**)&h2_16,g_h2_16);
  cudaGetSymbolAddress((void**)&ww,   g_ww);
  cudaGetSymbolAddress((void**)&wq,   g_wq);
  cudaGetSymbolAddress((void**)&wk,   g_wk);
  cudaGetSymbolAddress((void**)&wv,   g_wv);
  cudaGetSymbolAddress((void**)&wo,   g_wo);

  cudaFuncSetAttribute(gemm_mma, cudaFuncAttributeMaxDynamicSharedMemorySize, GEMM_SMEM);
  cudaFuncSetAttribute(gemm_qkv, cudaFuncAttributeMaxDynamicSharedMemorySize, GEMM_SMEM);
  cudaFuncSetAttribute(attn_mma, cudaFuncAttributeMaxDynamicSharedMemorySize, AT_SMEM);

  QKVArgs qa;
  qa.w0=wq; qa.w1=wk; qa.w2=wv;
  qa.bias0=bq; qa.bias1=bk; qa.bias2=bv;
  qa.c0=q16; qa.c1=k16; qa.c2=v16;

  PrepArgs pa;
  pa.w[0]=W_w; pa.w[1]=Wq; pa.w[2]=Wk; pa.w[3]=Wv; pa.w[4]=Wo;
  pa.t[0]=ww; pa.t[1]=wq; pa.t[2]=wk; pa.t[3]=wv; pa.t[4]=wo;
  pa.x = x; pa.x16 = x16;

  prep_kernel<<<5376,256>>>(pa);
  gemm_mma<<<dim3(4,32),512,GEMM_SMEM>>>(x16, ww, W_b, hp16, 0);
  ln_f16<<<1024,256>>>(hp16, lng, lnb, h16);
  gemm_qkv<<<dim3(12,32),512,GEMM_SMEM>>>(h16, qa);
  attn_mma<<<dim3(4,8,16),256,AT_SMEM>>>(q16,k16,v16,adj,ua,c16);
  gemm_mma<<<dim3(4,32),512,GEMM_SMEM>>>(c16, wo, bo, h2_16, 1);
  gate_kernel<<<1024,256>>>(x, h2_16, gw, gbb, out);
}

// round 14
// speedup vs baseline: 1.0601x; 1.0440x over previous
#include <cuda_runtime.h>
#include <cuda_fp16.h>
#include <cstdint>

// Problem constants
#define MROWS 8192
#define DM 512

// ---------------- scratch (static device arrays; no cudaMalloc allowed) ----
static __device__ __half g_x16[MROWS*DM];
static __device__ __half g_hp16[MROWS*DM];   // pre-LN h (fp16)
static __device__ __half g_h16[MROWS*DM];    // post-LN h (fp16)
static __device__ __half g_q16[MROWS*DM], g_k16[MROWS*DM], g_v16[MROWS*DM];
static __device__ __half g_c16[MROWS*DM];    // attention ctx
static __device__ __half g_h2_16[MROWS*DM];  // relu(ctx@Wo+bo)
// fp16 transposed weights ([n,k] so D = A·B^T = A·W)
static __device__ __half g_ww[DM*DM], g_wq[DM*DM], g_wk[DM*DM], g_wv[DM*DM], g_wo[DM*DM];

__device__ __forceinline__ uint32_t s2u(const void* p){
  return (uint32_t)__cvta_generic_to_shared(p);
}

// ---------------- mma.sync helpers -----------------------------------------
__device__ __forceinline__ void ldsm4(uint32_t* r, uint32_t addr){
  asm volatile("ldmatrix.sync.aligned.m8n8.x4.shared.b16 {%0,%1,%2,%3}, [%4];"
   : "=r"(r[0]),"=r"(r[1]),"=r"(r[2]),"=r"(r[3]) : "r"(addr));
}
__device__ __forceinline__ void ldsm4t(uint32_t* r, uint32_t addr){
  asm volatile("ldmatrix.sync.aligned.m8n8.x4.trans.shared.b16 {%0,%1,%2,%3}, [%4];"
   : "=r"(r[0]),"=r"(r[1]),"=r"(r[2]),"=r"(r[3]) : "r"(addr));
}
__device__ __forceinline__ void mma16816(float* d, const uint32_t* a, const uint32_t* b){
  asm volatile("mma.sync.aligned.m16n8k16.row.col.f32.f16.f16.f32 "
    "{%0,%1,%2,%3}, {%4,%5,%6,%7}, {%8,%9}, {%0,%1,%2,%3};"
    : "+f"(d[0]),"+f"(d[1]),"+f"(d[2]),"+f"(d[3])
    : "r"(a[0]),"r"(a[1]),"r"(a[2]),"r"(a[3]), "r"(b[0]),"r"(b[1]));
}

// fast exp: fp32 accuracy ~2.4e-6, runs on fma/alu pipes (no MUFU)
__device__ __forceinline__ float fexp(float x){
  float y = x * 1.44269504f;
  int   ki = __float2int_rn(y);
  float f  = y - (float)ki;
  float p = 1.333355815e-3f;
  p = fmaf(p, f, 9.618129107e-3f);
  p = fmaf(p, f, 5.550410866e-2f);
  p = fmaf(p, f, 2.402265069e-1f);
  p = fmaf(p, f, 6.931471806e-1f);
  p = fmaf(p, f, 1.0f);
  return p * __int_as_float((ki + 127) << 23);
}

// ---------------- GEMM core: CTA 256x128, 16 warps (4x4), warp tile 64x32 --
// C16[8192,512] = A @ W^T(+bias). BK=64, 512 threads, 3-stage cp.async ring.
#define SA 72
#define A2BYTES (256*SA*2)           // 36864
#define B2BYTES (128*SA*2)           // 18432
#define STG2 (A2BYTES + B2BYTES)     // 55296
#define NSTG 3
#define GEMM_SMEM (NSTG*STG2)        // 165888
#define NC 8

struct GemmCore {
  uint32_t sbase;
  int m0, n0, tid, lane, warpM, warpN;
  float acc[4][4][4];

  __device__ __forceinline__ void init(uint32_t sb, int m0_, int n0_){
    sbase = sb; m0 = m0_; n0 = n0_;
    tid = threadIdx.x; lane = tid & 31;
    int wid = tid >> 5; warpM = wid >> 2; warpN = wid & 3;
#pragma unroll
    for (int i=0;i<4;i++)
#pragma unroll
      for (int j=0;j<4;j++)
#pragma unroll
        for (int r=0;r<4;r++) acc[i][j][r]=0.f;
  }

  __device__ __forceinline__ void load_chunk(int s, int c,
      const __half* A, const __half* W){
    const int kk0 = c * 64;
    const uint32_t da = sbase + s*STG2;
    const uint32_t db = da + A2BYTES;
#pragma unroll
    for (int i=0;i<4;i++){
      int u = tid + i*512;
      int row = u >> 3, cc = u & 7;
      asm volatile("cp.async.cg.shared.global [%0], [%1], 16;"
        :: "r"(da + (uint32_t)(row*144 + cc*16)),
           "l"(A + (size_t)(m0+row)*512 + kk0 + cc*8));
    }
#pragma unroll
    for (int i=0;i<2;i++){
      int u = tid + i*512;
      int row = u >> 3, cc = u & 7;
      asm volatile("cp.async.cg.shared.global [%0], [%1], 16;"
        :: "r"(db + (uint32_t)(row*144 + cc*16)),
           "l"(W + (size_t)(n0+row)*512 + kk0 + cc*8));
    }
    asm volatile("cp.async.commit_group;" ::: "memory");
  }

  __device__ __forceinline__ void compute(int s){
    const uint32_t abase = sbase + s*STG2
        + (uint32_t)((warpM*64 + (lane & 15))*SA*2 + (lane >> 4)*16);
    const uint32_t bbase = sbase + s*STG2 + A2BYTES;
    const int n_off = ((lane >> 4) & 1) * 8 + (lane & 7);
    const int k_off = ((lane >> 3) & 1) * 8;
    uint32_t boff[2];
#pragma unroll
    for (int nip=0; nip<2; nip++)
      boff[nip] = bbase + (uint32_t)(((warpN*32 + nip*16 + n_off)*SA + k_off)*2);
#pragma unroll
    for (int k16=0; k16<4; k16++){
      uint32_t af[4][4];
#pragma unroll
      for (int mf=0; mf<4; mf++)
        ldsm4(af[mf], abase + (uint32_t)(mf*16*SA*2) + k16*32);
      uint32_t bf[2][4];
#pragma unroll
      for (int nip=0; nip<2; nip++)
        ldsm4(bf[nip], boff[nip] + k16*32);
#pragma unroll
      for (int mf=0; mf<4; mf++)
#pragma unroll
        for (int nip=0; nip<2; nip++){
          mma16816(acc[mf][2*nip],   af[mf], bf[nip]);
          mma16816(acc[mf][2*nip+1], af[mf], bf[nip]+2);
        }
    }
  }

  __device__ __forceinline__ void run(const __half* A, const __half* W){
    load_chunk(0, 0, A, W);
    load_chunk(1, 1, A, W);
    for (int c=0; c<NC; c++){
      if (c < NC-1) asm volatile("cp.async.wait_group 1;" ::: "memory");
      else          asm volatile("cp.async.wait_group 0;" ::: "memory");
      __syncthreads();
      if (c+2 < NC) load_chunk((c+2)%NSTG, c+2, A, W);
      compute(c%NSTG);
    }
  }

  // fp16 output; relu optional
  __device__ __forceinline__ void epilogue(const float* bias, __half* C16, int relu){
    const int g  = lane >> 2;
    const int tg = lane & 3;
#pragma unroll
    for (int mf=0; mf<4; mf++){
      const int row = m0 + warpM*64 + mf*16 + g;
#pragma unroll
      for (int ni=0; ni<4; ni++){
        const int col = n0 + warpN*32 + ni*8 + tg*2;
        const float b0 = bias[col], b1 = bias[col+1];
        float v[4] = {acc[mf][ni][0]+b0, acc[mf][ni][1]+b1,
                      acc[mf][ni][2]+b0, acc[mf][ni][3]+b1};
        if (relu){
#pragma unroll
          for (int e=0;e<4;e++) v[e] = fmaxf(v[e],0.f);
        }
        *reinterpret_cast<__half2*>(&C16[(size_t)row*512+col]) =
            __halves2half2(__float2half(v[0]), __float2half(v[1]));
        *reinterpret_cast<__half2*>(&C16[(size_t)(row+8)*512+col]) =
            __halves2half2(__float2half(v[2]), __float2half(v[3]));
      }
    }
  }
};

__global__ __launch_bounds__(512,1) void gemm_mma(
    const __half* __restrict__ A, const __half* __restrict__ W,
    const float* __restrict__ bias, __half* __restrict__ C16, int relu)
{
  extern __shared__ __align__(16) char smem_raw[];
  GemmCore core;
  core.init(s2u(smem_raw), blockIdx.y*256, blockIdx.x*128);
  core.run(A, W);
  core.epilogue(bias, C16, relu);
}

// Fused QKV: grid (12, 32); weight = blockIdx.x>>2, n-tile = blockIdx.x&3.
struct QKVArgs {
  const __half *w0,*w1,*w2;
  const float *bias0,*bias1,*bias2;
  __half *c0,*c1,*c2;
};

__global__ __launch_bounds__(512,1) void gemm_qkv(
    const __half* __restrict__ A, QKVArgs a)
{
  extern __shared__ __align__(16) char smem_raw[];
  const int w = blockIdx.x >> 2;
  const __half* W    = (w==0) ? a.w0 : (w==1) ? a.w1 : a.w2;
  const float* bias  = (w==0) ? a.bias0 : (w==1) ? a.bias1 : a.bias2;
  __half* C16        = (w==0) ? a.c0 : (w==1) ? a.c1 : a.c2;
  GemmCore core;
  core.init(s2u(smem_raw), blockIdx.y*256, (blockIdx.x & 3)*128);
  core.run(A, W);
  core.epilogue(bias, C16, 0);
}

// ---------------- prep: 5 weight transposes + x fp32->fp16, one launch -----
struct PrepArgs {
  const float* w[5];
  __half* t[5];
  const float* x;
  __half* x16;
};

__global__ __launch_bounds__(256) void prep_kernel(PrepArgs a)
{
  const int bx = blockIdx.x;
  if (bx < 1280){
    __shared__ float t[32][33];
    const int wsel = bx >> 8;          // 0..4
    const int tile = bx & 255;         // 16x16 tiles
    const int bxx = (tile & 15) * 32;  // n
    const int byy = (tile >> 4) * 32;  // k
    const float* W = a.w[wsel];
    __half* T      = a.t[wsel];
    const int txx = threadIdx.x & 31, tyy = threadIdx.x >> 5;
#pragma unroll
    for (int i=tyy;i<32;i+=8)
      t[i][txx] = W[(size_t)(byy+i)*512 + bxx + txx];
    __syncthreads();
#pragma unroll
    for (int i=tyy;i<32;i+=8)
      T[(size_t)(bxx+i)*512 + byy + txx] = __float2half(t[txx][i]);
  } else {
    int i = (bx - 1280)*256 + threadIdx.x;   // over float4 quads
    float4 v = reinterpret_cast<const float4*>(a.x)[i];
    reinterpret_cast<__half2*>(a.x16)[2*i]   = __halves2half2(__float2half(v.x), __float2half(v.y));
    reinterpret_cast<__half2*>(a.x16)[2*i+1] = __halves2half2(__float2half(v.z), __float2half(v.w));
  }
}

// ---------------- LayerNorm: one warp per row (no smem, no barriers) -------
__global__ __launch_bounds__(256) void ln_f16(
    const __half* __restrict__ hp, const float* __restrict__ g,
    const float* __restrict__ b, __half* __restrict__ h16)
{
  const int w = threadIdx.x >> 5, lane = threadIdx.x & 31;
  const int row = blockIdx.x*8 + w;
  const __half2* hr = reinterpret_cast<const __half2*>(hp + (size_t)row*512);
  float v0[8], v1[8];
  float s = 0.f;
#pragma unroll
  for (int i=0;i<8;i++){
    __half2 hv = hr[lane + i*32];
    v0[i] = __low2float(hv); v1[i] = __high2float(hv);
    s += v0[i] + v1[i];
  }
#pragma unroll
  for (int o=16;o;o>>=1) s += __shfl_xor_sync(0xffffffffu,s,o);
  const float mu = s * (1.f/512.f);
  float q = 0.f;
#pragma unroll
  for (int i=0;i<8;i++){
    v0[i] -= mu; v1[i] -= mu;
    q += v0[i]*v0[i] + v1[i]*v1[i];
  }
#pragma unroll
  for (int o=16;o;o>>=1) q += __shfl_xor_sync(0xffffffffu,q,o);
  const float rstd = rsqrtf(q * (1.f/512.f) + 1e-5f);
  __half2* orow = reinterpret_cast<__half2*>(h16 + (size_t)row*512);
#pragma unroll
  for (int i=0;i<8;i++){
    const int c = 2*(lane + i*32);
    float o0 = v0[i]*rstd*g[c]   + b[c];
    float o1 = v1[i]*rstd*g[c+1] + b[c+1];
    orow[lane + i*32] = __halves2half2(__float2half(o0), __float2half(o1));
  }
}

// ---------------- Tensor-core flash attention (fp16, no-max softmax) -------
// Per CTA: (b, h, 128 q rows). 256 threads, 8 warps (4 warpM x 2 warpN).
// 2 CTAs/SM: smem 2x106KB = 217KB < 228KB; regs forced to 128.
#define QB 144
#define PB 272
#define OQ  0
#define OK0 18432
#define OK1 36864
#define OV  55296
#define OP  73728
#define OLP 108544
#define AT_SMEM (OLP + 1024)

__device__ __forceinline__ void at_load_tile(uint32_t sdst,
    const __half* __restrict__ g, int row0, int col0, int tid)
{
  int row = tid >> 1, half = tid & 1;
  uint32_t d = sdst + (uint32_t)(row*QB + half*64);
  const __half* s = g + (size_t)(row0+row)*512 + col0 + half*32;
#pragma unroll
  for (int j=0;j<4;j++)
    asm volatile("cp.async.cg.shared.global [%0], [%1], 16;" :: "r"(d + j*16), "l"(s + j*8));
}

__global__ __launch_bounds__(256,2) void attn_mma(
    const __half* __restrict__ q16, const __half* __restrict__ k16,
    const __half* __restrict__ v16,
    const float* __restrict__ adj, const int* __restrict__ use_adj,
    __half* __restrict__ c16)
{
  extern __shared__ __align__(16) char sm8[];
  const uint32_t sb = s2u(sm8);
  float* lp = reinterpret_cast<float*>(sm8 + OLP);

  const int tid = threadIdx.x, lane = tid & 31, wid = tid >> 5;
  const int warpM = wid >> 1, warpN = wid & 1;
  const int q0 = blockIdx.x * 128;
  const int hh = blockIdx.y, bb = blockIdx.z;
  const int ua = use_adj[0];
  const int col0 = hh * 64;
  const int rowg0 = bb * 512;

  at_load_tile(sb+OQ, q16, rowg0+q0, col0, tid);
  lp[tid] = 0.f;

  float oacc[2][4][4];
#pragma unroll
  for (int i=0;i<2;i++)
#pragma unroll
    for (int j=0;j<4;j++)
#pragma unroll
      for (int e=0;e<4;e++) oacc[i][j][e]=0.f;

  const uint32_t a_off  = (uint32_t)((lane&15)*QB + (lane>>4)*16);
  const uint32_t b_off  = (uint32_t)((((lane>>4)&1)*8 + (lane&7))*QB + ((lane>>3)&1)*16);
  const uint32_t ap_off = (uint32_t)((lane&15)*PB + (lane>>4)*16);

  const int r0 = warpM*32 + (lane>>2);
  const int cb = warpN*64 + 2*(lane&3);

  for (int kb=0; kb<4; kb++){
    const int krow0 = rowg0 + kb*128;
    if (kb == 0){
      at_load_tile(sb+OK0, k16, krow0, col0, tid);
      at_load_tile(sb+OV,  v16, krow0, col0, tid);
      asm volatile("cp.async.commit_group;" ::: "memory");
      asm volatile("cp.async.wait_group 0;" ::: "memory");
      __syncthreads();
    }

    // ---- S = Q K^T ----
    float sacc[2][8][4];
#pragma unroll
    for (int i=0;i<2;i++)
#pragma unroll
      for (int j=0;j<8;j++)
#pragma unroll
        for (int e=0;e<4;e++) sacc[i][j][e]=0.f;

    {
      const uint32_t qb_ = sb + OQ + (uint32_t)(warpM*32*QB) + a_off;
      const uint32_t kb_ = sb + ((kb&1) ? OK1 : OK0) + (uint32_t)(warpN*64*QB) + b_off;
#pragma unroll
      for (int k16i=0;k16i<4;k16i++){
        uint32_t af[2][4];
        ldsm4(af[0], qb_ + k16i*32);
        ldsm4(af[1], qb_ + 16*QB + k16i*32);
#pragma unroll
        for (int nf=0;nf<4;nf++){
          uint32_t bf[4];
          ldsm4(bf, kb_ + (uint32_t)(nf*16*QB) + k16i*32);
          mma16816(sacc[0][2*nf],   af[0], bf);
          mma16816(sacc[0][2*nf+1], af[0], bf+2);
          mma16816(sacc[1][2*nf],   af[1], bf);
          mma16816(sacc[1][2*nf+1], af[1], bf+2);
        }
      }
    }

    // ---- scale*adj, exp, row sums, store P fp16 ----
#pragma unroll
    for (int mi=0;mi<2;mi++){
      const int rr = r0 + mi*16;
      float rs0 = 0.f, rs8 = 0.f;
#pragma unroll
      for (int nf=0;nf<8;nf++){
        const int cc = cb + nf*8;
        float m0=1.f,m1=1.f,m2=1.f,m3=1.f;
        if (ua){
          const float* ar = adj + ((size_t)(rowg0+q0+rr))*512 + kb*128 + cc;
          float2 a01 = *reinterpret_cast<const float2*>(ar);
          float2 a23 = *reinterpret_cast<const float2*>(ar + 8*512);
          m0=a01.x; m1=a01.y; m2=a23.x; m3=a23.y;
        }
        float p0 = fexp(sacc[mi][nf][0]*0.125f*m0);
        float p1 = fexp(sacc[mi][nf][1]*0.125f*m1);
        float p2 = fexp(sacc[mi][nf][2]*0.125f*m2);
        float p3 = fexp(sacc[mi][nf][3]*0.125f*m3);
        rs0 += p0+p1;  rs8 += p2+p3;
        __half2 t0 = __halves2half2(__float2half(p0), __float2half(p1));
        __half2 t1 = __halves2half2(__float2half(p2), __float2half(p3));
        uint32_t ph01 = *reinterpret_cast<uint32_t*>(&t0);
        uint32_t ph23 = *reinterpret_cast<uint32_t*>(&t1);
        uint32_t pa = sb + OP + (uint32_t)(rr*PB + cc*2);
        asm volatile("st.shared.b32 [%0], %1;" :: "r"(pa), "r"(ph01));
        asm volatile("st.shared.b32 [%0], %1;" :: "r"(pa + 8*PB), "r"(ph23));
      }
      rs0 += __shfl_xor_sync(0xffffffffu, rs0, 1);
      rs0 += __shfl_xor_sync(0xffffffffu, rs0, 2);
      rs8 += __shfl_xor_sync(0xffffffffu, rs8, 1);
      rs8 += __shfl_xor_sync(0xffffffffu, rs8, 2);
      if ((lane&3)==0){
        lp[warpN*128 + rr]     += rs0;
        lp[warpN*128 + rr + 8] += rs8;
      }
    }
    __syncthreads();   // P visible; K[kb&1] free

    if (kb < 3){       // prefetch next K into other buffer while PV runs
      at_load_tile(sb + ((kb&1) ? OK0 : OK1), k16, krow0+128, col0, tid);
      asm volatile("cp.async.commit_group;" ::: "memory");
    }

    // ---- O += P V, V^T via ldmatrix.trans ----
    {
      const uint32_t pb2 = sb + OP + (uint32_t)(warpM*32*PB) + ap_off;
      const uint32_t vb2 = sb + OV + (uint32_t)((lane&15)*QB + (warpN*32 + (lane>>4)*8)*2);
#pragma unroll
      for (int k16i=0;k16i<8;k16i++){
        uint32_t af[2][4];
        ldsm4(af[0], pb2 + k16i*32);
        ldsm4(af[1], pb2 + 16*PB + k16i*32);
#pragma unroll
        for (int nf=0;nf<2;nf++){
          uint32_t bf[4];
          ldsm4t(bf, vb2 + (uint32_t)(k16i*16*QB) + (uint32_t)(nf*16*2));
          mma16816(oacc[0][2*nf],   af[0], bf);
          mma16816(oacc[0][2*nf+1], af[0], bf+2);
          mma16816(oacc[1][2*nf],   af[1], bf);
          mma16816(oacc[1][2*nf+1], af[1], bf+2);
        }
      }
    }
    __syncthreads();   // V reads complete

    if (kb < 3){
      at_load_tile(sb+OV, v16, krow0+128, col0, tid);
      asm volatile("cp.async.commit_group;" ::: "memory");
      asm volatile("cp.async.wait_group 0;" ::: "memory");
      __syncthreads();
    }
  }

  // ---- epilogue: normalize, store fp16 ctx ----
  if (tid < 128) lp[tid] = 1.f / (lp[tid] + lp[128 + tid]);
  __syncthreads();
#pragma unroll
  for (int mi=0;mi<2;mi++){
    const int rr = r0 + mi*16;
    const float inv0 = lp[rr], inv8 = lp[rr+8];
    const size_t rga = (size_t)(rowg0 + q0 + rr);
#pragma unroll
    for (int nf=0;nf<4;nf++){
      const int colg = col0 + warpN*32 + nf*8 + 2*(lane&3);
      *reinterpret_cast<__half2*>(&c16[rga*512 + colg]) =
          __halves2half2(__float2half(oacc[mi][nf][0]*inv0),
                         __float2half(oacc[mi][nf][1]*inv0));
      *reinterpret_cast<__half2*>(&c16[(rga+8)*512 + colg]) =
          __halves2half2(__float2half(oacc[mi][nf][2]*inv8),
                         __float2half(oacc[mi][nf][3]*inv8));
    }
  }
}

// ---------------- Gate + blend: out = c*x + (1-c)*h2 (h2 fp16) -------------
__global__ void gate_kernel(const float* __restrict__ x, const __half* __restrict__ h2,
    const float* __restrict__ gw, const float* __restrict__ gb, float* __restrict__ out)
{
  const int w = threadIdx.x>>5, lane = threadIdx.x&31;
  const int row = blockIdx.x*8 + w;
  const float* xr = x  + (size_t)row*512;
  const __half* hr = h2 + (size_t)row*512;
  float hf[16];
  float s = 0.f;
#pragma unroll
  for (int i=0;i<16;i++){
    int c = i*32 + lane;
    hf[i] = __half2float(hr[c]);
    s += xr[c]*gw[c] + hf[i]*gw[512+c];
  }
#pragma unroll
  for (int off=16;off;off>>=1) s += __shfl_xor_sync(0xffffffffu,s,off);
  s += gb[0];
  float coeff = 1.f/(1.f+__expf(-s));
  float* orow = out + (size_t)row*512;
#pragma unroll
  for (int i=0;i<16;i++){
    int c = i*32+lane;
    orow[c] = coeff*xr[c] + (1.f-coeff)*hf[i];
  }
}

// ---------------- launch ---------------------------------------------------
extern "C" void kernel_launch(void* const* d_in, const int* in_sizes, int n_in,
                              void* d_out, int out_size)
{
  const float* x   = (const float*)d_in[0];
  const float* adj = (const float*)d_in[1];
  const float* W_w = (const float*)d_in[2];
  const float* W_b = (const float*)d_in[3];
  const float* lng = (const float*)d_in[4];
  const float* lnb = (const float*)d_in[5];
  const float* Wq  = (const float*)d_in[6];
  const float* bq  = (const float*)d_in[7];
  const float* Wk  = (const float*)d_in[8];
  const float* bk  = (const float*)d_in[9];
  const float* Wv  = (const float*)d_in[10];
  const float* bv  = (const float*)d_in[11];
  const float* Wo  = (const float*)d_in[12];
  const float* bo  = (const float*)d_in[13];
  const float* gw  = (const float*)d_in[14];
  const float* gbb = (const float*)d_in[15];
  const int*   ua  = (const int*)d_in[16];
  float* out = (float*)d_out;

  __half *x16,*hp16,*h16,*q16,*k16,*v16,*c16,*h2_16,*ww,*wq,*wk,*wv,*wo;
  cudaGetSymbolAddress((void**)&x16,  g_x16);
  cudaGetSymbolAddress((void**)&hp16, g_hp16);
  cudaGetSymbolAddress((void**)&h16,  g_h16);
  cudaGetSymbolAddress((void**)&q16,  g_q16);
  cudaGetSymbolAddress((void**)&k16,  g_k16);
  cudaGetSymbolAddress((void**)&v16,  g_v16);
  cudaGetSymbolAddress((void**)&c16,  g_c16);
  cudaGetSymbolAddress((void**)&h2_16,g_h2_16);
  cudaGetSymbolAddress((void**)&ww,   g_ww);
  cudaGetSymbolAddress((void**)&wq,   g_wq);
  cudaGetSymbolAddress((void**)&wk,   g_wk);
  cudaGetSymbolAddress((void**)&wv,   g_wv);
  cudaGetSymbolAddress((void**)&wo,   g_wo);

  cudaFuncSetAttribute(gemm_mma, cudaFuncAttributeMaxDynamicSharedMemorySize, GEMM_SMEM);
  cudaFuncSetAttribute(gemm_qkv, cudaFuncAttributeMaxDynamicSharedMemorySize, GEMM_SMEM);
  cudaFuncSetAttribute(attn_mma, cudaFuncAttributeMaxDynamicSharedMemorySize, AT_SMEM);

  QKVArgs qa;
  qa.w0=wq; qa.w1=wk; qa.w2=wv;
  qa.bias0=bq; qa.bias1=bk; qa.bias2=bv;
  qa.c0=q16; qa.c1=k16; qa.c2=v16;

  PrepArgs pa;
  pa.w[0]=W_w; pa.w[1]=Wq; pa.w[2]=Wk; pa.w[3]=Wv; pa.w[4]=Wo;
  pa.t[0]=ww; pa.t[1]=wq; pa.t[2]=wk; pa.t[3]=wv; pa.t[4]=wo;
  pa.x = x; pa.x16 = x16;

  prep_kernel<<<5376,256>>>(pa);
  gemm_mma<<<dim3(4,32),512,GEMM_SMEM>>>(x16, ww, W_b, hp16, 0);
  ln_f16<<<1024,256>>>(hp16, lng, lnb, h16);
  gemm_qkv<<<dim3(12,32),512,GEMM_SMEM>>>(h16, qa);
  attn_mma<<<dim3(4,8,16),256,AT_SMEM>>>(q16,k16,v16,adj,ua,c16);
  gemm_mma<<<dim3(4,32),512,GEMM_SMEM>>>(c16, wo, bo, h2_16, 1);
  gate_kernel<<<1024,256>>>(x, h2_16, gw, gbb, out);
}

// round 15
// speedup vs baseline: 1.0627x; 1.0025x over previous
#include <cuda_runtime.h>
#include <cuda_fp16.h>
#include <cstdint>

// Problem constants
#define MROWS 8192
#define DM 512

// ---------------- scratch (static device arrays; no cudaMalloc allowed) ----
static __device__ __half g_x16[MROWS*DM];
static __device__ __half g_hp16[MROWS*DM];   // pre-LN h (fp16)
static __device__ __half g_h16[MROWS*DM];    // post-LN h (fp16)
static __device__ __half g_q16[MROWS*DM], g_k16[MROWS*DM], g_v16[MROWS*DM];
static __device__ __half g_c16[MROWS*DM];    // attention ctx
static __device__ __half g_h2_16[MROWS*DM];  // relu(ctx@Wo+bo)
// fp16 transposed weights ([n,k] so D = A·B^T = A·W)
static __device__ __half g_ww[DM*DM], g_wq[DM*DM], g_wk[DM*DM], g_wv[DM*DM], g_wo[DM*DM];

__device__ __forceinline__ uint32_t s2u(const void* p){
  return (uint32_t)__cvta_generic_to_shared(p);
}

// ---------------- mma.sync helpers -----------------------------------------
__device__ __forceinline__ void ldsm4(uint32_t* r, uint32_t addr){
  asm volatile("ldmatrix.sync.aligned.m8n8.x4.shared.b16 {%0,%1,%2,%3}, [%4];"
   : "=r"(r[0]),"=r"(r[1]),"=r"(r[2]),"=r"(r[3]) : "r"(addr));
}
__device__ __forceinline__ void ldsm4t(uint32_t* r, uint32_t addr){
  asm volatile("ldmatrix.sync.aligned.m8n8.x4.trans.shared.b16 {%0,%1,%2,%3}, [%4];"
   : "=r"(r[0]),"=r"(r[1]),"=r"(r[2]),"=r"(r[3]) : "r"(addr));
}
__device__ __forceinline__ void mma16816(float* d, const uint32_t* a, const uint32_t* b){
  asm volatile("mma.sync.aligned.m16n8k16.row.col.f32.f16.f16.f32 "
    "{%0,%1,%2,%3}, {%4,%5,%6,%7}, {%8,%9}, {%0,%1,%2,%3};"
    : "+f"(d[0]),"+f"(d[1]),"+f"(d[2]),"+f"(d[3])
    : "r"(a[0]),"r"(a[1]),"r"(a[2]),"r"(a[3]), "r"(b[0]),"r"(b[1]));
}

// fast exp: fp32 accuracy ~2.4e-6, runs on fma/alu pipes (no MUFU)
__device__ __forceinline__ float fexp(float x){
  float y = x * 1.44269504f;
  int   ki = __float2int_rn(y);
  float f  = y - (float)ki;
  float p = 1.333355815e-3f;
  p = fmaf(p, f, 9.618129107e-3f);
  p = fmaf(p, f, 5.550410866e-2f);
  p = fmaf(p, f, 2.402265069e-1f);
  p = fmaf(p, f, 6.931471806e-1f);
  p = fmaf(p, f, 1.0f);
  return p * __int_as_float((ki + 127) << 23);
}

// ---------------- GEMM core: CTA 256x128, 16 warps (4x4), BK=128 ----------
// C16[8192,512] = A @ W^T(+bias). 512 threads, 2-stage ring, 4 chunks only.
#define SA2 136                       // halves per smem row (272 B)
#define A2BYTES (256*272)             // 69632
#define B2BYTES (128*272)             // 34816
#define STG2 (A2BYTES + B2BYTES)      // 104448
#define NSTG 2
#define GEMM_SMEM (NSTG*STG2)         // 208896
#define NC 4

struct GemmCore {
  uint32_t sbase;
  int m0, n0, tid, lane, warpM, warpN;
  float acc[4][4][4];

  __device__ __forceinline__ void init(uint32_t sb, int m0_, int n0_){
    sbase = sb; m0 = m0_; n0 = n0_;
    tid = threadIdx.x; lane = tid & 31;
    int wid = tid >> 5; warpM = wid >> 2; warpN = wid & 3;
#pragma unroll
    for (int i=0;i<4;i++)
#pragma unroll
      for (int j=0;j<4;j++)
#pragma unroll
        for (int r=0;r<4;r++) acc[i][j][r]=0.f;
  }

  __device__ __forceinline__ void load_chunk(int s, int c,
      const __half* A, const __half* W){
    const int kk0 = c * 128;
    const uint32_t da = sbase + s*STG2;
    const uint32_t db = da + A2BYTES;
    // A: 256 rows x 128 halves = 4096 16B units, 8 per thread
#pragma unroll
    for (int i=0;i<8;i++){
      int u = tid + i*512;
      int row = u >> 4, cc = u & 15;
      asm volatile("cp.async.cg.shared.global [%0], [%1], 16;"
        :: "r"(da + (uint32_t)(row*272 + cc*16)),
           "l"(A + (size_t)(m0+row)*512 + kk0 + cc*8));
    }
    // B: 128 rows x 128 halves = 2048 units, 4 per thread
#pragma unroll
    for (int i=0;i<4;i++){
      int u = tid + i*512;
      int row = u >> 4, cc = u & 15;
      asm volatile("cp.async.cg.shared.global [%0], [%1], 16;"
        :: "r"(db + (uint32_t)(row*272 + cc*16)),
           "l"(W + (size_t)(n0+row)*512 + kk0 + cc*8));
    }
    asm volatile("cp.async.commit_group;" ::: "memory");
  }

  __device__ __forceinline__ void compute(int s){
    const uint32_t abase = sbase + s*STG2
        + (uint32_t)((warpM*64 + (lane & 15))*SA2*2 + (lane >> 4)*16);
    const uint32_t bbase = sbase + s*STG2 + A2BYTES;
    const int n_off = ((lane >> 4) & 1) * 8 + (lane & 7);
    const int k_off = ((lane >> 3) & 1) * 8;
    uint32_t boff[2];
#pragma unroll
    for (int nip=0; nip<2; nip++)
      boff[nip] = bbase + (uint32_t)(((warpN*32 + nip*16 + n_off)*SA2 + k_off)*2);
#pragma unroll
    for (int k16=0; k16<8; k16++){
      uint32_t af[4][4];
#pragma unroll
      for (int mf=0; mf<4; mf++)
        ldsm4(af[mf], abase + (uint32_t)(mf*16*SA2*2) + k16*32);
      uint32_t bf[2][4];
#pragma unroll
      for (int nip=0; nip<2; nip++)
        ldsm4(bf[nip], boff[nip] + k16*32);
#pragma unroll
      for (int mf=0; mf<4; mf++)
#pragma unroll
        for (int nip=0; nip<2; nip++){
          mma16816(acc[mf][2*nip],   af[mf], bf[nip]);
          mma16816(acc[mf][2*nip+1], af[mf], bf[nip]+2);
        }
    }
  }

  __device__ __forceinline__ void run(const __half* A, const __half* W){
    load_chunk(0, 0, A, W);
    for (int c=0; c<NC; c++){
      if (c+1 < NC) load_chunk((c+1)&1, c+1, A, W);
      if (c+1 < NC) asm volatile("cp.async.wait_group 1;" ::: "memory");
      else          asm volatile("cp.async.wait_group 0;" ::: "memory");
      __syncthreads();
      compute(c&1);
      __syncthreads();
    }
  }

  // fp16 output; relu optional
  __device__ __forceinline__ void epilogue(const float* bias, __half* C16, int relu){
    const int g  = lane >> 2;
    const int tg = lane & 3;
#pragma unroll
    for (int mf=0; mf<4; mf++){
      const int row = m0 + warpM*64 + mf*16 + g;
#pragma unroll
      for (int ni=0; ni<4; ni++){
        const int col = n0 + warpN*32 + ni*8 + tg*2;
        const float b0 = bias[col], b1 = bias[col+1];
        float v[4] = {acc[mf][ni][0]+b0, acc[mf][ni][1]+b1,
                      acc[mf][ni][2]+b0, acc[mf][ni][3]+b1};
        if (relu){
#pragma unroll
          for (int e=0;e<4;e++) v[e] = fmaxf(v[e],0.f);
        }
        *reinterpret_cast<__half2*>(&C16[(size_t)row*512+col]) =
            __halves2half2(__float2half(v[0]), __float2half(v[1]));
        *reinterpret_cast<__half2*>(&C16[(size_t)(row+8)*512+col]) =
            __halves2half2(__float2half(v[2]), __float2half(v[3]));
      }
    }
  }
};

__global__ __launch_bounds__(512,1) void gemm_mma(
    const __half* __restrict__ A, const __half* __restrict__ W,
    const float* __restrict__ bias, __half* __restrict__ C16, int relu)
{
  extern __shared__ __align__(16) char smem_raw[];
  GemmCore core;
  core.init(s2u(smem_raw), blockIdx.y*256, blockIdx.x*128);
  core.run(A, W);
  core.epilogue(bias, C16, relu);
}

// Fused QKV: grid (12, 32); weight = blockIdx.x>>2, n-tile = blockIdx.x&3.
struct QKVArgs {
  const __half *w0,*w1,*w2;
  const float *bias0,*bias1,*bias2;
  __half *c0,*c1,*c2;
};

__global__ __launch_bounds__(512,1) void gemm_qkv(
    const __half* __restrict__ A, QKVArgs a)
{
  extern __shared__ __align__(16) char smem_raw[];
  const int w = blockIdx.x >> 2;
  const __half* W    = (w==0) ? a.w0 : (w==1) ? a.w1 : a.w2;
  const float* bias  = (w==0) ? a.bias0 : (w==1) ? a.bias1 : a.bias2;
  __half* C16        = (w==0) ? a.c0 : (w==1) ? a.c1 : a.c2;
  GemmCore core;
  core.init(s2u(smem_raw), blockIdx.y*256, (blockIdx.x & 3)*128);
  core.run(A, W);
  core.epilogue(bias, C16, 0);
}

// ---------------- prep: 5 weight transposes + x fp32->fp16, one launch -----
struct PrepArgs {
  const float* w[5];
  __half* t[5];
  const float* x;
  __half* x16;
};

__global__ __launch_bounds__(256) void prep_kernel(PrepArgs a)
{
  const int bx = blockIdx.x;
  if (bx < 1280){
    __shared__ float t[32][33];
    const int wsel = bx >> 8;          // 0..4
    const int tile = bx & 255;         // 16x16 tiles
    const int bxx = (tile & 15) * 32;  // n
    const int byy = (tile >> 4) * 32;  // k
    const float* W = a.w[wsel];
    __half* T      = a.t[wsel];
    const int txx = threadIdx.x & 31, tyy = threadIdx.x >> 5;
#pragma unroll
    for (int i=tyy;i<32;i+=8)
      t[i][txx] = W[(size_t)(byy+i)*512 + bxx + txx];
    __syncthreads();
#pragma unroll
    for (int i=tyy;i<32;i+=8)
      T[(size_t)(bxx+i)*512 + byy + txx] = __float2half(t[txx][i]);
  } else {
    int i = (bx - 1280)*256 + threadIdx.x;   // over float4 quads
    float4 v = reinterpret_cast<const float4*>(a.x)[i];
    reinterpret_cast<__half2*>(a.x16)[2*i]   = __halves2half2(__float2half(v.x), __float2half(v.y));
    reinterpret_cast<__half2*>(a.x16)[2*i+1] = __halves2half2(__float2half(v.z), __float2half(v.w));
  }
}

// ---------------- LayerNorm: one warp per row (no smem, no barriers) -------
__global__ __launch_bounds__(256) void ln_f16(
    const __half* __restrict__ hp, const float* __restrict__ g,
    const float* __restrict__ b, __half* __restrict__ h16)
{
  const int w = threadIdx.x >> 5, lane = threadIdx.x & 31;
  const int row = blockIdx.x*8 + w;
  const __half2* hr = reinterpret_cast<const __half2*>(hp + (size_t)row*512);
  float v0[8], v1[8];
  float s = 0.f;
#pragma unroll
  for (int i=0;i<8;i++){
    __half2 hv = hr[lane + i*32];
    v0[i] = __low2float(hv); v1[i] = __high2float(hv);
    s += v0[i] + v1[i];
  }
#pragma unroll
  for (int o=16;o;o>>=1) s += __shfl_xor_sync(0xffffffffu,s,o);
  const float mu = s * (1.f/512.f);
  float q = 0.f;
#pragma unroll
  for (int i=0;i<8;i++){
    v0[i] -= mu; v1[i] -= mu;
    q += v0[i]*v0[i] + v1[i]*v1[i];
  }
#pragma unroll
  for (int o=16;o;o>>=1) q += __shfl_xor_sync(0xffffffffu,q,o);
  const float rstd = rsqrtf(q * (1.f/512.f) + 1e-5f);
  __half2* orow = reinterpret_cast<__half2*>(h16 + (size_t)row*512);
#pragma unroll
  for (int i=0;i<8;i++){
    const int c = 2*(lane + i*32);
    float o0 = v0[i]*rstd*g[c]   + b[c];
    float o1 = v1[i]*rstd*g[c+1] + b[c+1];
    orow[lane + i*32] = __halves2half2(__float2half(o0), __float2half(o1));
  }
}

// ---------------- Tensor-core flash attention (fp16, no-max softmax) -------
// Per CTA: (b, h, 128 q rows). 256 threads, 8 warps (4 warpM x 2 warpN).
// 2 CTAs/SM: smem 2x106KB = 217KB < 228KB; regs forced to 128.
#define QB 144
#define PB 272
#define OQ  0
#define OK0 18432
#define OK1 36864
#define OV  55296
#define OP  73728
#define OLP 108544
#define AT_SMEM (OLP + 1024)

__device__ __forceinline__ void at_load_tile(uint32_t sdst,
    const __half* __restrict__ g, int row0, int col0, int tid)
{
  int row = tid >> 1, half = tid & 1;
  uint32_t d = sdst + (uint32_t)(row*QB + half*64);
  const __half* s = g + (size_t)(row0+row)*512 + col0 + half*32;
#pragma unroll
  for (int j=0;j<4;j++)
    asm volatile("cp.async.cg.shared.global [%0], [%1], 16;" :: "r"(d + j*16), "l"(s + j*8));
}

__global__ __launch_bounds__(256,2) void attn_mma(
    const __half* __restrict__ q16, const __half* __restrict__ k16,
    const __half* __restrict__ v16,
    const float* __restrict__ adj, const int* __restrict__ use_adj,
    __half* __restrict__ c16)
{
  extern __shared__ __align__(16) char sm8[];
  const uint32_t sb = s2u(sm8);
  float* lp = reinterpret_cast<float*>(sm8 + OLP);

  const int tid = threadIdx.x, lane = tid & 31, wid = tid >> 5;
  const int warpM = wid >> 1, warpN = wid & 1;
  const int q0 = blockIdx.x * 128;
  const int hh = blockIdx.y, bb = blockIdx.z;
  const int ua = use_adj[0];
  const int col0 = hh * 64;
  const int rowg0 = bb * 512;

  at_load_tile(sb+OQ, q16, rowg0+q0, col0, tid);
  lp[tid] = 0.f;

  float oacc[2][4][4];
#pragma unroll
  for (int i=0;i<2;i++)
#pragma unroll
    for (int j=0;j<4;j++)
#pragma unroll
      for (int e=0;e<4;e++) oacc[i][j][e]=0.f;

  const uint32_t a_off  = (uint32_t)((lane&15)*QB + (lane>>4)*16);
  const uint32_t b_off  = (uint32_t)((((lane>>4)&1)*8 + (lane&7))*QB + ((lane>>3)&1)*16);
  const uint32_t ap_off = (uint32_t)((lane&15)*PB + (lane>>4)*16);

  const int r0 = warpM*32 + (lane>>2);
  const int cb = warpN*64 + 2*(lane&3);

  for (int kb=0; kb<4; kb++){
    const int krow0 = rowg0 + kb*128;
    if (kb == 0){
      at_load_tile(sb+OK0, k16, krow0, col0, tid);
      at_load_tile(sb+OV,  v16, krow0, col0, tid);
      asm volatile("cp.async.commit_group;" ::: "memory");
      asm volatile("cp.async.wait_group 0;" ::: "memory");
      __syncthreads();
    }

    // ---- S = Q K^T ----
    float sacc[2][8][4];
#pragma unroll
    for (int i=0;i<2;i++)
#pragma unroll
      for (int j=0;j<8;j++)
#pragma unroll
        for (int e=0;e<4;e++) sacc[i][j][e]=0.f;

    {
      const uint32_t qb_ = sb + OQ + (uint32_t)(warpM*32*QB) + a_off;
      const uint32_t kb_ = sb + ((kb&1) ? OK1 : OK0) + (uint32_t)(warpN*64*QB) + b_off;
#pragma unroll
      for (int k16i=0;k16i<4;k16i++){
        uint32_t af[2][4];
        ldsm4(af[0], qb_ + k16i*32);
        ldsm4(af[1], qb_ + 16*QB + k16i*32);
#pragma unroll
        for (int nf=0;nf<4;nf++){
          uint32_t bf[4];
          ldsm4(bf, kb_ + (uint32_t)(nf*16*QB) + k16i*32);
          mma16816(sacc[0][2*nf],   af[0], bf);
          mma16816(sacc[0][2*nf+1], af[0], bf+2);
          mma16816(sacc[1][2*nf],   af[1], bf);
          mma16816(sacc[1][2*nf+1], af[1], bf+2);
        }
      }
    }

    // ---- scale*adj, exp, row sums, store P fp16 ----
#pragma unroll
    for (int mi=0;mi<2;mi++){
      const int rr = r0 + mi*16;
      float rs0 = 0.f, rs8 = 0.f;
#pragma unroll
      for (int nf=0;nf<8;nf++){
        const int cc = cb + nf*8;
        float m0=1.f,m1=1.f,m2=1.f,m3=1.f;
        if (ua){
          const float* ar = adj + ((size_t)(rowg0+q0+rr))*512 + kb*128 + cc;
          float2 a01 = *reinterpret_cast<const float2*>(ar);
          float2 a23 = *reinterpret_cast<const float2*>(ar + 8*512);
          m0=a01.x; m1=a01.y; m2=a23.x; m3=a23.y;
        }
        float p0 = fexp(sacc[mi][nf][0]*0.125f*m0);
        float p1 = fexp(sacc[mi][nf][1]*0.125f*m1);
        float p2 = fexp(sacc[mi][nf][2]*0.125f*m2);
        float p3 = fexp(sacc[mi][nf][3]*0.125f*m3);
        rs0 += p0+p1;  rs8 += p2+p3;
        __half2 t0 = __halves2half2(__float2half(p0), __float2half(p1));
        __half2 t1 = __halves2half2(__float2half(p2), __float2half(p3));
        uint32_t ph01 = *reinterpret_cast<uint32_t*>(&t0);
        uint32_t ph23 = *reinterpret_cast<uint32_t*>(&t1);
        uint32_t pa = sb + OP + (uint32_t)(rr*PB + cc*2);
        asm volatile("st.shared.b32 [%0], %1;" :: "r"(pa), "r"(ph01));
        asm volatile("st.shared.b32 [%0], %1;" :: "r"(pa + 8*PB), "r"(ph23));
      }
      rs0 += __shfl_xor_sync(0xffffffffu, rs0, 1);
      rs0 += __shfl_xor_sync(0xffffffffu, rs0, 2);
      rs8 += __shfl_xor_sync(0xffffffffu, rs8, 1);
      rs8 += __shfl_xor_sync(0xffffffffu, rs8, 2);
      if ((lane&3)==0){
        lp[warpN*128 + rr]     += rs0;
        lp[warpN*128 + rr + 8] += rs8;
      }
    }
    __syncthreads();   // P visible; K[kb&1] free

    if (kb < 3){       // prefetch next K into other buffer while PV runs
      at_load_tile(sb + ((kb&1) ? OK0 : OK1), k16, krow0+128, col0, tid);
      asm volatile("cp.async.commit_group;" ::: "memory");
    }

    // ---- O += P V, V^T via ldmatrix.trans ----
    {
      const uint32_t pb2 = sb + OP + (uint32_t)(warpM*32*PB) + ap_off;
      const uint32_t vb2 = sb + OV + (uint32_t)((lane&15)*QB + (warpN*32 + (lane>>4)*8)*2);
#pragma unroll
      for (int k16i=0;k16i<8;k16i++){
        uint32_t af[2][4];
        ldsm4(af[0], pb2 + k16i*32);
        ldsm4(af[1], pb2 + 16*PB + k16i*32);
#pragma unroll
        for (int nf=0;nf<2;nf++){
          uint32_t bf[4];
          ldsm4t(bf, vb2 + (uint32_t)(k16i*16*QB) + (uint32_t)(nf*16*2));
          mma16816(oacc[0][2*nf],   af[0], bf);
          mma16816(oacc[0][2*nf+1], af[0], bf+2);
          mma16816(oacc[1][2*nf],   af[1], bf);
          mma16816(oacc[1][2*nf+1], af[1], bf+2);
        }
      }
    }
    __syncthreads();   // V reads complete

    if (kb < 3){
      at_load_tile(sb+OV, v16, krow0+128, col0, tid);
      asm volatile("cp.async.commit_group;" ::: "memory");
      asm volatile("cp.async.wait_group 0;" ::: "memory");
      __syncthreads();
    }
  }

  // ---- epilogue: normalize, store fp16 ctx ----
  if (tid < 128) lp[tid] = 1.f / (lp[tid] + lp[128 + tid]);
  __syncthreads();
#pragma unroll
  for (int mi=0;mi<2;mi++){
    const int rr = r0 + mi*16;
    const float inv0 = lp[rr], inv8 = lp[rr+8];
    const size_t rga = (size_t)(rowg0 + q0 + rr);
#pragma unroll
    for (int nf=0;nf<4;nf++){
      const int colg = col0 + warpN*32 + nf*8 + 2*(lane&3);
      *reinterpret_cast<__half2*>(&c16[rga*512 + colg]) =
          __halves2half2(__float2half(oacc[mi][nf][0]*inv0),
                         __float2half(oacc[mi][nf][1]*inv0));
      *reinterpret_cast<__half2*>(&c16[(rga+8)*512 + colg]) =
          __halves2half2(__float2half(oacc[mi][nf][2]*inv8),
                         __float2half(oacc[mi][nf][3]*inv8));
    }
  }
}

// ---------------- Gate + blend: out = c*x + (1-c)*h2 (h2 fp16) -------------
__global__ void gate_kernel(const float* __restrict__ x, const __half* __restrict__ h2,
    const float* __restrict__ gw, const float* __restrict__ gb, float* __restrict__ out)
{
  const int w = threadIdx.x>>5, lane = threadIdx.x&31;
  const int row = blockIdx.x*8 + w;
  const float* xr = x  + (size_t)row*512;
  const __half* hr = h2 + (size_t)row*512;
  float hf[16];
  float s = 0.f;
#pragma unroll
  for (int i=0;i<16;i++){
    int c = i*32 + lane;
    hf[i] = __half2float(hr[c]);
    s += xr[c]*gw[c] + hf[i]*gw[512+c];
  }
#pragma unroll
  for (int off=16;off;off>>=1) s += __shfl_xor_sync(0xffffffffu,s,off);
  s += gb[0];
  float coeff = 1.f/(1.f+__expf(-s));
  float* orow = out + (size_t)row*512;
#pragma unroll
  for (int i=0;i<16;i++){
    int c = i*32+lane;
    orow[c] = coeff*xr[c] + (1.f-coeff)*hf[i];
  }
}

// ---------------- launch ---------------------------------------------------
extern "C" void kernel_launch(void* const* d_in, const int* in_sizes, int n_in,
                              void* d_out, int out_size)
{
  const float* x   = (const float*)d_in[0];
  const float* adj = (const float*)d_in[1];
  const float* W_w = (const float*)d_in[2];
  const float* W_b = (const float*)d_in[3];
  const float* lng = (const float*)d_in[4];
  const float* lnb = (const float*)d_in[5];
  const float* Wq  = (const float*)d_in[6];
  const float* bq  = (const float*)d_in[7];
  const float* Wk  = (const float*)d_in[8];
  const float* bk  = (const float*)d_in[9];
  const float* Wv  = (const float*)d_in[10];
  const float* bv  = (const float*)d_in[11];
  const float* Wo  = (const float*)d_in[12];
  const float* bo  = (const float*)d_in[13];
  const float* gw  = (const float*)d_in[14];
  const float* gbb = (const float*)d_in[15];
  const int*   ua  = (const int*)d_in[16];
  float* out = (float*)d_out;

  __half *x16,*hp16,*h16,*q16,*k16,*v16,*c16,*h2_16,*ww,*wq,*wk,*wv,*wo;
  cudaGetSymbolAddress((void**)&x16,  g_x16);
  cudaGetSymbolAddress((void**)&hp16, g_hp16);
  cudaGetSymbolAddress((void**)&h16,  g_h16);
  cudaGetSymbolAddress((void**)&q16,  g_q16);
  cudaGetSymbolAddress((void**)&k16,  g_k16);
  cudaGetSymbolAddress((void**)&v16,  g_v16);
  cudaGetSymbolAddress((void**)&c16,  g_c16);
  cudaGetSymbolAddress((void**)&h2_16,g_h2_16);
  cudaGetSymbolAddress((void**)&ww,   g_ww);
  cudaGetSymbolAddress((void**)&wq,   g_wq);
  cudaGetSymbolAddress((void**)&wk,   g_wk);
  cudaGetSymbolAddress((void**)&wv,   g_wv);
  cudaGetSymbolAddress((void**)&wo,   g_wo);

  cudaFuncSetAttribute(gemm_mma, cudaFuncAttributeMaxDynamicSharedMemorySize, GEMM_SMEM);
  cudaFuncSetAttribute(gemm_qkv, cudaFuncAttributeMaxDynamicSharedMemorySize, GEMM_SMEM);
  cudaFuncSetAttribute(attn_mma, cudaFuncAttributeMaxDynamicSharedMemorySize, AT_SMEM);

  QKVArgs qa;
  qa.w0=wq; qa.w1=wk; qa.w2=wv;
  qa.bias0=bq; qa.bias1=bk; qa.bias2=bv;
  qa.c0=q16; qa.c1=k16; qa.c2=v16;

  PrepArgs pa;
  pa.w[0]=W_w; pa.w[1]=Wq; pa.w[2]=Wk; pa.w[3]=Wv; pa.w[4]=Wo;
  pa.t[0]=ww; pa.t[1]=wq; pa.t[2]=wk; pa.t[3]=wv; pa.t[4]=wo;
  pa.x = x; pa.x16 = x16;

  prep_kernel<<<5376,256>>>(pa);
  gemm_mma<<<dim3(4,32),512,GEMM_SMEM>>>(x16, ww, W_b, hp16, 0);
  ln_f16<<<1024,256>>>(hp16, lng, lnb, h16);
  gemm_qkv<<<dim3(12,32),512,GEMM_SMEM>>>(h16, qa);
  attn_mma<<<dim3(4,8,16),256,AT_SMEM>>>(q16,k16,v16,adj,ua,c16);
  gemm_mma<<<dim3(4,32),512,GEMM_SMEM>>>(c16, wo, bo, h2_16, 1);
  gate_kernel<<<1024,256>>>(x, h2_16, gw, gbb, out);
}

// round 16
// speedup vs baseline: 1.0862x; 1.0220x over previous
#include <cuda_runtime.h>
#include <cuda_fp16.h>
#include <cstdint>

// Problem constants
#define MROWS 8192
#define DM 512

// ---------------- scratch (static device arrays; no cudaMalloc allowed) ----
static __device__ __half g_x16[MROWS*DM];
static __device__ __half g_hp16[MROWS*DM];   // pre-LN h (fp16)
static __device__ __half g_h16[MROWS*DM];    // post-LN h (fp16)
static __device__ __half g_q16[MROWS*DM], g_k16[MROWS*DM], g_v16[MROWS*DM];
static __device__ __half g_c16[MROWS*DM];    // attention ctx
static __device__ __half g_h2_16[MROWS*DM];  // relu(ctx@Wo+bo)
// fp16 transposed weights ([n,k] so D = A·B^T = A·W)
static __device__ __half g_ww[DM*DM], g_wq[DM*DM], g_wk[DM*DM], g_wv[DM*DM], g_wo[DM*DM];

__device__ __forceinline__ uint32_t s2u(const void* p){
  return (uint32_t)__cvta_generic_to_shared(p);
}

// ---------------- mma.sync helpers -----------------------------------------
__device__ __forceinline__ void ldsm4(uint32_t* r, uint32_t addr){
  asm volatile("ldmatrix.sync.aligned.m8n8.x4.shared.b16 {%0,%1,%2,%3}, [%4];"
   : "=r"(r[0]),"=r"(r[1]),"=r"(r[2]),"=r"(r[3]) : "r"(addr));
}
__device__ __forceinline__ void ldsm4t(uint32_t* r, uint32_t addr){
  asm volatile("ldmatrix.sync.aligned.m8n8.x4.trans.shared.b16 {%0,%1,%2,%3}, [%4];"
   : "=r"(r[0]),"=r"(r[1]),"=r"(r[2]),"=r"(r[3]) : "r"(addr));
}
__device__ __forceinline__ void mma16816(float* d, const uint32_t* a, const uint32_t* b){
  asm volatile("mma.sync.aligned.m16n8k16.row.col.f32.f16.f16.f32 "
    "{%0,%1,%2,%3}, {%4,%5,%6,%7}, {%8,%9}, {%0,%1,%2,%3};"
    : "+f"(d[0]),"+f"(d[1]),"+f"(d[2]),"+f"(d[3])
    : "r"(a[0]),"r"(a[1]),"r"(a[2]),"r"(a[3]), "r"(b[0]),"r"(b[1]));
}

// fast exp: fp32 accuracy ~2.4e-6, runs on fma/alu pipes (no MUFU)
__device__ __forceinline__ float fexp(float x){
  float y = x * 1.44269504f;
  int   ki = __float2int_rn(y);
  float f  = y - (float)ki;
  float p = 1.333355815e-3f;
  p = fmaf(p, f, 9.618129107e-3f);
  p = fmaf(p, f, 5.550410866e-2f);
  p = fmaf(p, f, 2.402265069e-1f);
  p = fmaf(p, f, 6.931471806e-1f);
  p = fmaf(p, f, 1.0f);
  return p * __int_as_float((ki + 127) << 23);
}

// ---------------- GEMM core: CTA 128x128, 8 warps (2x4), warp tile 64x32 ---
// 2 CTAs/SM (independent barrier domains de-convoy the tensor pipe).
// BK=64, 256 threads, 3-stage cp.async ring, 8 chunks.
#define SA 72
#define ABYTES (128*144)             // 18432
#define STG2 (2*ABYTES)              // 36864
#define NSTG 3
#define GEMM_SMEM (NSTG*STG2)        // 110592 (x2 CTA = 221184 <= 227KB)
#define NC 8

struct GemmCore {
  uint32_t sbase;
  int m0, n0, tid, lane, warpM, warpN;
  float acc[4][4][4];

  __device__ __forceinline__ void init(uint32_t sb, int m0_, int n0_){
    sbase = sb; m0 = m0_; n0 = n0_;
    tid = threadIdx.x; lane = tid & 31;
    int wid = tid >> 5; warpM = wid >> 2; warpN = wid & 3;
#pragma unroll
    for (int i=0;i<4;i++)
#pragma unroll
      for (int j=0;j<4;j++)
#pragma unroll
        for (int r=0;r<4;r++) acc[i][j][r]=0.f;
  }

  __device__ __forceinline__ void load_chunk(int s, int c,
      const __half* A, const __half* W){
    const int kk0 = c * 64;
    const uint32_t da = sbase + s*STG2;
    const uint32_t db = da + ABYTES;
    // A: 128 rows x 64 halves = 1024 16B units, 4 per thread
#pragma unroll
    for (int i=0;i<4;i++){
      int u = tid + i*256;
      int row = u >> 3, cc = u & 7;
      asm volatile("cp.async.cg.shared.global [%0], [%1], 16;"
        :: "r"(da + (uint32_t)(row*144 + cc*16)),
           "l"(A + (size_t)(m0+row)*512 + kk0 + cc*8));
    }
    // B: 128 rows x 64 halves = 1024 units, 4 per thread
#pragma unroll
    for (int i=0;i<4;i++){
      int u = tid + i*256;
      int row = u >> 3, cc = u & 7;
      asm volatile("cp.async.cg.shared.global [%0], [%1], 16;"
        :: "r"(db + (uint32_t)(row*144 + cc*16)),
           "l"(W + (size_t)(n0+row)*512 + kk0 + cc*8));
    }
    asm volatile("cp.async.commit_group;" ::: "memory");
  }

  __device__ __forceinline__ void compute(int s){
    const uint32_t abase = sbase + s*STG2
        + (uint32_t)((warpM*64 + (lane & 15))*SA*2 + (lane >> 4)*16);
    const uint32_t bbase = sbase + s*STG2 + ABYTES;
    const int n_off = ((lane >> 4) & 1) * 8 + (lane & 7);
    const int k_off = ((lane >> 3) & 1) * 8;
    uint32_t boff[2];
#pragma unroll
    for (int nip=0; nip<2; nip++)
      boff[nip] = bbase + (uint32_t)(((warpN*32 + nip*16 + n_off)*SA + k_off)*2);
#pragma unroll
    for (int k16=0; k16<4; k16++){
      uint32_t af[4][4];
#pragma unroll
      for (int mf=0; mf<4; mf++)
        ldsm4(af[mf], abase + (uint32_t)(mf*16*SA*2) + k16*32);
      uint32_t bf[2][4];
#pragma unroll
      for (int nip=0; nip<2; nip++)
        ldsm4(bf[nip], boff[nip] + k16*32);
#pragma unroll
      for (int mf=0; mf<4; mf++)
#pragma unroll
        for (int nip=0; nip<2; nip++){
          mma16816(acc[mf][2*nip],   af[mf], bf[nip]);
          mma16816(acc[mf][2*nip+1], af[mf], bf[nip]+2);
        }
    }
  }

  __device__ __forceinline__ void run(const __half* A, const __half* W){
    load_chunk(0, 0, A, W);
    load_chunk(1, 1, A, W);
    for (int c=0; c<NC; c++){
      if (c < NC-1) asm volatile("cp.async.wait_group 1;" ::: "memory");
      else          asm volatile("cp.async.wait_group 0;" ::: "memory");
      __syncthreads();
      if (c+2 < NC) load_chunk((c+2)%NSTG, c+2, A, W);
      compute(c%NSTG);
    }
  }

  // fp16 output; relu optional
  __device__ __forceinline__ void epilogue(const float* bias, __half* C16, int relu){
    const int g  = lane >> 2;
    const int tg = lane & 3;
#pragma unroll
    for (int mf=0; mf<4; mf++){
      const int row = m0 + warpM*64 + mf*16 + g;
#pragma unroll
      for (int ni=0; ni<4; ni++){
        const int col = n0 + warpN*32 + ni*8 + tg*2;
        const float b0 = bias[col], b1 = bias[col+1];
        float v[4] = {acc[mf][ni][0]+b0, acc[mf][ni][1]+b1,
                      acc[mf][ni][2]+b0, acc[mf][ni][3]+b1};
        if (relu){
#pragma unroll
          for (int e=0;e<4;e++) v[e] = fmaxf(v[e],0.f);
        }
        *reinterpret_cast<__half2*>(&C16[(size_t)row*512+col]) =
            __halves2half2(__float2half(v[0]), __float2half(v[1]));
        *reinterpret_cast<__half2*>(&C16[(size_t)(row+8)*512+col]) =
            __halves2half2(__float2half(v[2]), __float2half(v[3]));
      }
    }
  }
};

__global__ __launch_bounds__(256,2) void gemm_mma(
    const __half* __restrict__ A, const __half* __restrict__ W,
    const float* __restrict__ bias, __half* __restrict__ C16, int relu)
{
  extern __shared__ __align__(16) char smem_raw[];
  GemmCore core;
  core.init(s2u(smem_raw), blockIdx.y*128, blockIdx.x*128);
  core.run(A, W);
  core.epilogue(bias, C16, relu);
}

// Fused QKV: grid (12, 64); weight = blockIdx.x>>2, n-tile = blockIdx.x&3.
struct QKVArgs {
  const __half *w0,*w1,*w2;
  const float *bias0,*bias1,*bias2;
  __half *c0,*c1,*c2;
};

__global__ __launch_bounds__(256,2) void gemm_qkv(
    const __half* __restrict__ A, QKVArgs a)
{
  extern __shared__ __align__(16) char smem_raw[];
  const int w = blockIdx.x >> 2;
  const __half* W    = (w==0) ? a.w0 : (w==1) ? a.w1 : a.w2;
  const float* bias  = (w==0) ? a.bias0 : (w==1) ? a.bias1 : a.bias2;
  __half* C16        = (w==0) ? a.c0 : (w==1) ? a.c1 : a.c2;
  GemmCore core;
  core.init(s2u(smem_raw), blockIdx.y*128, (blockIdx.x & 3)*128);
  core.run(A, W);
  core.epilogue(bias, C16, 0);
}

// ---------------- prep: 5 weight transposes + x fp32->fp16, one launch -----
struct PrepArgs {
  const float* w[5];
  __half* t[5];
  const float* x;
  __half* x16;
};

__global__ __launch_bounds__(256) void prep_kernel(PrepArgs a)
{
  const int bx = blockIdx.x;
  if (bx < 1280){
    __shared__ float t[32][33];
    const int wsel = bx >> 8;          // 0..4
    const int tile = bx & 255;         // 16x16 tiles
    const int bxx = (tile & 15) * 32;  // n
    const int byy = (tile >> 4) * 32;  // k
    const float* W = a.w[wsel];
    __half* T      = a.t[wsel];
    const int txx = threadIdx.x & 31, tyy = threadIdx.x >> 5;
#pragma unroll
    for (int i=tyy;i<32;i+=8)
      t[i][txx] = W[(size_t)(byy+i)*512 + bxx + txx];
    __syncthreads();
#pragma unroll
    for (int i=tyy;i<32;i+=8)
      T[(size_t)(bxx+i)*512 + byy + txx] = __float2half(t[txx][i]);
  } else {
    int i = (bx - 1280)*256 + threadIdx.x;   // over float4 quads
    float4 v = reinterpret_cast<const float4*>(a.x)[i];
    reinterpret_cast<__half2*>(a.x16)[2*i]   = __halves2half2(__float2half(v.x), __float2half(v.y));
    reinterpret_cast<__half2*>(a.x16)[2*i+1] = __halves2half2(__float2half(v.z), __float2half(v.w));
  }
}

// ---------------- LayerNorm: one warp per row (no smem, no barriers) -------
__global__ __launch_bounds__(256) void ln_f16(
    const __half* __restrict__ hp, const float* __restrict__ g,
    const float* __restrict__ b, __half* __restrict__ h16)
{
  const int w = threadIdx.x >> 5, lane = threadIdx.x & 31;
  const int row = blockIdx.x*8 + w;
  const __half2* hr = reinterpret_cast<const __half2*>(hp + (size_t)row*512);
  float v0[8], v1[8];
  float s = 0.f;
#pragma unroll
  for (int i=0;i<8;i++){
    __half2 hv = hr[lane + i*32];
    v0[i] = __low2float(hv); v1[i] = __high2float(hv);
    s += v0[i] + v1[i];
  }
#pragma unroll
  for (int o=16;o;o>>=1) s += __shfl_xor_sync(0xffffffffu,s,o);
  const float mu = s * (1.f/512.f);
  float q = 0.f;
#pragma unroll
  for (int i=0;i<8;i++){
    v0[i] -= mu; v1[i] -= mu;
    q += v0[i]*v0[i] + v1[i]*v1[i];
  }
#pragma unroll
  for (int o=16;o;o>>=1) q += __shfl_xor_sync(0xffffffffu,q,o);
  const float rstd = rsqrtf(q * (1.f/512.f) + 1e-5f);
  __half2* orow = reinterpret_cast<__half2*>(h16 + (size_t)row*512);
#pragma unroll
  for (int i=0;i<8;i++){
    const int c = 2*(lane + i*32);
    float o0 = v0[i]*rstd*g[c]   + b[c];
    float o1 = v1[i]*rstd*g[c+1] + b[c+1];
    orow[lane + i*32] = __halves2half2(__float2half(o0), __float2half(o1));
  }
}

// ---------------- Tensor-core flash attention (fp16, no-max softmax) -------
// Per CTA: (b, h, 128 q rows). 256 threads, 8 warps (4 warpM x 2 warpN).
// 2 CTAs/SM: smem 2x106KB = 217KB; regs forced to 128.
#define QB 144
#define PB 272
#define OQ  0
#define OK0 18432
#define OK1 36864
#define OV  55296
#define OP  73728
#define OLP 108544
#define AT_SMEM (OLP + 1024)

__device__ __forceinline__ void at_load_tile(uint32_t sdst,
    const __half* __restrict__ g, int row0, int col0, int tid)
{
  int row = tid >> 1, half = tid & 1;
  uint32_t d = sdst + (uint32_t)(row*QB + half*64);
  const __half* s = g + (size_t)(row0+row)*512 + col0 + half*32;
#pragma unroll
  for (int j=0;j<4;j++)
    asm volatile("cp.async.cg.shared.global [%0], [%1], 16;" :: "r"(d + j*16), "l"(s + j*8));
}

__global__ __launch_bounds__(256,2) void attn_mma(
    const __half* __restrict__ q16, const __half* __restrict__ k16,
    const __half* __restrict__ v16,
    const float* __restrict__ adj, const int* __restrict__ use_adj,
    __half* __restrict__ c16)
{
  extern __shared__ __align__(16) char sm8[];
  const uint32_t sb = s2u(sm8);
  float* lp = reinterpret_cast<float*>(sm8 + OLP);

  const int tid = threadIdx.x, lane = tid & 31, wid = tid >> 5;
  const int warpM = wid >> 1, warpN = wid & 1;
  const int q0 = blockIdx.x * 128;
  const int hh = blockIdx.y, bb = blockIdx.z;
  const int ua = use_adj[0];
  const int col0 = hh * 64;
  const int rowg0 = bb * 512;

  at_load_tile(sb+OQ, q16, rowg0+q0, col0, tid);
  lp[tid] = 0.f;

  float oacc[2][4][4];
#pragma unroll
  for (int i=0;i<2;i++)
#pragma unroll
    for (int j=0;j<4;j++)
#pragma unroll
      for (int e=0;e<4;e++) oacc[i][j][e]=0.f;

  const uint32_t a_off  = (uint32_t)((lane&15)*QB + (lane>>4)*16);
  const uint32_t b_off  = (uint32_t)((((lane>>4)&1)*8 + (lane&7))*QB + ((lane>>3)&1)*16);
  const uint32_t ap_off = (uint32_t)((lane&15)*PB + (lane>>4)*16);

  const int r0 = warpM*32 + (lane>>2);
  const int cb = warpN*64 + 2*(lane&3);

  for (int kb=0; kb<4; kb++){
    const int krow0 = rowg0 + kb*128;
    if (kb == 0){
      at_load_tile(sb+OK0, k16, krow0, col0, tid);
      at_load_tile(sb+OV,  v16, krow0, col0, tid);
      asm volatile("cp.async.commit_group;" ::: "memory");
      asm volatile("cp.async.wait_group 0;" ::: "memory");
      __syncthreads();
    }

    // ---- S = Q K^T ----
    float sacc[2][8][4];
#pragma unroll
    for (int i=0;i<2;i++)
#pragma unroll
      for (int j=0;j<8;j++)
#pragma unroll
        for (int e=0;e<4;e++) sacc[i][j][e]=0.f;

    {
      const uint32_t qb_ = sb + OQ + (uint32_t)(warpM*32*QB) + a_off;
      const uint32_t kb_ = sb + ((kb&1) ? OK1 : OK0) + (uint32_t)(warpN*64*QB) + b_off;
#pragma unroll
      for (int k16i=0;k16i<4;k16i++){
        uint32_t af[2][4];
        ldsm4(af[0], qb_ + k16i*32);
        ldsm4(af[1], qb_ + 16*QB + k16i*32);
#pragma unroll
        for (int nf=0;nf<4;nf++){
          uint32_t bf[4];
          ldsm4(bf, kb_ + (uint32_t)(nf*16*QB) + k16i*32);
          mma16816(sacc[0][2*nf],   af[0], bf);
          mma16816(sacc[0][2*nf+1], af[0], bf+2);
          mma16816(sacc[1][2*nf],   af[1], bf);
          mma16816(sacc[1][2*nf+1], af[1], bf+2);
        }
      }
    }

    // ---- scale*adj, exp, row sums, store P fp16 ----
#pragma unroll
    for (int mi=0;mi<2;mi++){
      const int rr = r0 + mi*16;
      float rs0 = 0.f, rs8 = 0.f;
#pragma unroll
      for (int nf=0;nf<8;nf++){
        const int cc = cb + nf*8;
        float m0=1.f,m1=1.f,m2=1.f,m3=1.f;
        if (ua){
          const float* ar = adj + ((size_t)(rowg0+q0+rr))*512 + kb*128 + cc;
          float2 a01 = *reinterpret_cast<const float2*>(ar);
          float2 a23 = *reinterpret_cast<const float2*>(ar + 8*512);
          m0=a01.x; m1=a01.y; m2=a23.x; m3=a23.y;
        }
        float p0 = fexp(sacc[mi][nf][0]*0.125f*m0);
        float p1 = fexp(sacc[mi][nf][1]*0.125f*m1);
        float p2 = fexp(sacc[mi][nf][2]*0.125f*m2);
        float p3 = fexp(sacc[mi][nf][3]*0.125f*m3);
        rs0 += p0+p1;  rs8 += p2+p3;
        __half2 t0 = __halves2half2(__float2half(p0), __float2half(p1));
        __half2 t1 = __halves2half2(__float2half(p2), __float2half(p3));
        uint32_t ph01 = *reinterpret_cast<uint32_t*>(&t0);
        uint32_t ph23 = *reinterpret_cast<uint32_t*>(&t1);
        uint32_t pa = sb + OP + (uint32_t)(rr*PB + cc*2);
        asm volatile("st.shared.b32 [%0], %1;" :: "r"(pa), "r"(ph01));
        asm volatile("st.shared.b32 [%0], %1;" :: "r"(pa + 8*PB), "r"(ph23));
      }
      rs0 += __shfl_xor_sync(0xffffffffu, rs0, 1);
      rs0 += __shfl_xor_sync(0xffffffffu, rs0, 2);
      rs8 += __shfl_xor_sync(0xffffffffu, rs8, 1);
      rs8 += __shfl_xor_sync(0xffffffffu, rs8, 2);
      if ((lane&3)==0){
        lp[warpN*128 + rr]     += rs0;
        lp[warpN*128 + rr + 8] += rs8;
      }
    }
    __syncthreads();   // P visible; K[kb&1] free

    if (kb < 3){       // prefetch next K into other buffer while PV runs
      at_load_tile(sb + ((kb&1) ? OK0 : OK1), k16, krow0+128, col0, tid);
      asm volatile("cp.async.commit_group;" ::: "memory");
    }

    // ---- O += P V, V^T via ldmatrix.trans ----
    {
      const uint32_t pb2 = sb + OP + (uint32_t)(warpM*32*PB) + ap_off;
      const uint32_t vb2 = sb + OV + (uint32_t)((lane&15)*QB + (warpN*32 + (lane>>4)*8)*2);
#pragma unroll
      for (int k16i=0;k16i<8;k16i++){
        uint32_t af[2][4];
        ldsm4(af[0], pb2 + k16i*32);
        ldsm4(af[1], pb2 + 16*PB + k16i*32);
#pragma unroll
        for (int nf=0;nf<2;nf++){
          uint32_t bf[4];
          ldsm4t(bf, vb2 + (uint32_t)(k16i*16*QB) + (uint32_t)(nf*16*2));
          mma16816(oacc[0][2*nf],   af[0], bf);
          mma16816(oacc[0][2*nf+1], af[0], bf+2);
          mma16816(oacc[1][2*nf],   af[1], bf);
          mma16816(oacc[1][2*nf+1], af[1], bf+2);
        }
      }
    }
    __syncthreads();   // V reads complete

    if (kb < 3){
      at_load_tile(sb+OV, v16, krow0+128, col0, tid);
      asm volatile("cp.async.commit_group;" ::: "memory");
      asm volatile("cp.async.wait_group 0;" ::: "memory");
      __syncthreads();
    }
  }

  // ---- epilogue: normalize, store fp16 ctx ----
  if (tid < 128) lp[tid] = 1.f / (lp[tid] + lp[128 + tid]);
  __syncthreads();
#pragma unroll
  for (int mi=0;mi<2;mi++){
    const int rr = r0 + mi*16;
    const float inv0 = lp[rr], inv8 = lp[rr+8];
    const size_t rga = (size_t)(rowg0 + q0 + rr);
#pragma unroll
    for (int nf=0;nf<4;nf++){
      const int colg = col0 + warpN*32 + nf*8 + 2*(lane&3);
      *reinterpret_cast<__half2*>(&c16[rga*512 + colg]) =
          __halves2half2(__float2half(oacc[mi][nf][0]*inv0),
                         __float2half(oacc[mi][nf][1]*inv0));
      *reinterpret_cast<__half2*>(&c16[(rga+8)*512 + colg]) =
          __halves2half2(__float2half(oacc[mi][nf][2]*inv8),
                         __float2half(oacc[mi][nf][3]*inv8));
    }
  }
}

// ---------------- Gate + blend: out = c*x + (1-c)*h2 (h2 fp16) -------------
__global__ void gate_kernel(const float* __restrict__ x, const __half* __restrict__ h2,
    const float* __restrict__ gw, const float* __restrict__ gb, float* __restrict__ out)
{
  const int w = threadIdx.x>>5, lane = threadIdx.x&31;
  const int row = blockIdx.x*8 + w;
  const float* xr = x  + (size_t)row*512;
  const __half* hr = h2 + (size_t)row*512;
  float hf[16];
  float s = 0.f;
#pragma unroll
  for (int i=0;i<16;i++){
    int c = i*32 + lane;
    hf[i] = __half2float(hr[c]);
    s += xr[c]*gw[c] + hf[i]*gw[512+c];
  }
#pragma unroll
  for (int off=16;off;off>>=1) s += __shfl_xor_sync(0xffffffffu,s,off);
  s += gb[0];
  float coeff = 1.f/(1.f+__expf(-s));
  float* orow = out + (size_t)row*512;
#pragma unroll
  for (int i=0;i<16;i++){
    int c = i*32+lane;
    orow[c] = coeff*xr[c] + (1.f-coeff)*hf[i];
  }
}

// ---------------- launch ---------------------------------------------------
extern "C" void kernel_launch(void* const* d_in, const int* in_sizes, int n_in,
                              void* d_out, int out_size)
{
  const float* x   = (const float*)d_in[0];
  const float* adj = (const float*)d_in[1];
  const float* W_w = (const float*)d_in[2];
  const float* W_b = (const float*)d_in[3];
  const float* lng = (const float*)d_in[4];
  const float* lnb = (const float*)d_in[5];
  const float* Wq  = (const float*)d_in[6];
  const float* bq  = (const float*)d_in[7];
  const float* Wk  = (const float*)d_in[8];
  const float* bk  = (const float*)d_in[9];
  const float* Wv  = (const float*)d_in[10];
  const float* bv  = (const float*)d_in[11];
  const float* Wo  = (const float*)d_in[12];
  const float* bo  = (const float*)d_in[13];
  const float* gw  = (const float*)d_in[14];
  const float* gbb = (const float*)d_in[15];
  const int*   ua  = (const int*)d_in[16];
  float* out = (float*)d_out;

  __half *x16,*hp16,*h16,*q16,*k16,*v16,*c16,*h2_16,*ww,*wq,*wk,*wv,*wo;
  cudaGetSymbolAddress((void**)&x16,  g_x16);
  cudaGetSymbolAddress((void**)&hp16, g_hp16);
  cudaGetSymbolAddress((void**)&h16,  g_h16);
  cudaGetSymbolAddress((void**)&q16,  g_q16);
  cudaGetSymbolAddress((void**)&k16,  g_k16);
  cudaGetSymbolAddress((void**)&v16,  g_v16);
  cudaGetSymbolAddress((void**)&c16,  g_c16);
  cudaGetSymbolAddress((void**)&h2_16,g_h2_16);
  cudaGetSymbolAddress((void**)&ww,   g_ww);
  cudaGetSymbolAddress((void**)&wq,   g_wq);
  cudaGetSymbolAddress((void**)&wk,   g_wk);
  cudaGetSymbolAddress((void**)&wv,   g_wv);
  cudaGetSymbolAddress((void**)&wo,   g_wo);

  cudaFuncSetAttribute(gemm_mma, cudaFuncAttributeMaxDynamicSharedMemorySize, GEMM_SMEM);
  cudaFuncSetAttribute(gemm_qkv, cudaFuncAttributeMaxDynamicSharedMemorySize, GEMM_SMEM);
  cudaFuncSetAttribute(attn_mma, cudaFuncAttributeMaxDynamicSharedMemorySize, AT_SMEM);

  QKVArgs qa;
  qa.w0=wq; qa.w1=wk; qa.w2=wv;
  qa.bias0=bq; qa.bias1=bk; qa.bias2=bv;
  qa.c0=q16; qa.c1=k16; qa.c2=v16;

  PrepArgs pa;
  pa.w[0]=W_w; pa.w[1]=Wq; pa.w[2]=Wk; pa.w[3]=Wv; pa.w[4]=Wo;
  pa.t[0]=ww; pa.t[1]=wq; pa.t[2]=wk; pa.t[3]=wv; pa.t[4]=wo;
  pa.x = x; pa.x16 = x16;

  prep_kernel<<<5376,256>>>(pa);
  gemm_mma<<<dim3(4,64),256,GEMM_SMEM>>>(x16, ww, W_b, hp16, 0);
  ln_f16<<<1024,256>>>(hp16, lng, lnb, h16);
  gemm_qkv<<<dim3(12,64),256,GEMM_SMEM>>>(h16, qa);
  attn_mma<<<dim3(4,8,16),256,AT_SMEM>>>(q16,k16,v16,adj,ua,c16);
  gemm_mma<<<dim3(4,64),256,GEMM_SMEM>>>(c16, wo, bo, h2_16, 1);
  gate_kernel<<<1024,256>>>(x, h2_16, gw, gbb, out);
}

// round 17
// speedup vs baseline: 1.0992x; 1.0120x over previous
#include <cuda_runtime.h>
#include <cuda_fp16.h>
#include <cstdint>

// Problem constants
#define MROWS 8192
#define DM 512

// ---------------- scratch (static device arrays; no cudaMalloc allowed) ----
static __device__ __half g_x16[MROWS*DM];
static __device__ __half g_hp16[MROWS*DM];   // pre-LN h (fp16)
static __device__ __half g_h16[MROWS*DM];    // post-LN h (fp16)
static __device__ __half g_q16[MROWS*DM], g_k16[MROWS*DM], g_v16[MROWS*DM];
static __device__ __half g_c16[MROWS*DM];    // attention ctx
static __device__ __half g_h2_16[MROWS*DM];  // relu(ctx@Wo+bo)
// fp16 transposed weights ([n,k] so D = A·B^T = A·W)
static __device__ __half g_ww[DM*DM], g_wq[DM*DM], g_wk[DM*DM], g_wv[DM*DM], g_wo[DM*DM];

__device__ __forceinline__ uint32_t s2u(const void* p){
  return (uint32_t)__cvta_generic_to_shared(p);
}

// ---------------- PDL (programmatic dependent launch) ----------------------
__device__ __forceinline__ void gdc_wait(){
  asm volatile("griddepcontrol.wait;" ::: "memory");
}
__device__ __forceinline__ void gdc_launch(){
  asm volatile("griddepcontrol.launch_dependents;" ::: "memory");
}

// ---------------- mma.sync helpers -----------------------------------------
__device__ __forceinline__ void ldsm4(uint32_t* r, uint32_t addr){
  asm volatile("ldmatrix.sync.aligned.m8n8.x4.shared.b16 {%0,%1,%2,%3}, [%4];"
   : "=r"(r[0]),"=r"(r[1]),"=r"(r[2]),"=r"(r[3]) : "r"(addr));
}
__device__ __forceinline__ void ldsm4t(uint32_t* r, uint32_t addr){
  asm volatile("ldmatrix.sync.aligned.m8n8.x4.trans.shared.b16 {%0,%1,%2,%3}, [%4];"
   : "=r"(r[0]),"=r"(r[1]),"=r"(r[2]),"=r"(r[3]) : "r"(addr));
}
__device__ __forceinline__ void mma16816(float* d, const uint32_t* a, const uint32_t* b){
  asm volatile("mma.sync.aligned.m16n8k16.row.col.f32.f16.f16.f32 "
    "{%0,%1,%2,%3}, {%4,%5,%6,%7}, {%8,%9}, {%0,%1,%2,%3};"
    : "+f"(d[0]),"+f"(d[1]),"+f"(d[2]),"+f"(d[3])
    : "r"(a[0]),"r"(a[1]),"r"(a[2]),"r"(a[3]), "r"(b[0]),"r"(b[1]));
}

// fast exp: fp32 accuracy ~2.4e-6, runs on fma/alu pipes (no MUFU)
__device__ __forceinline__ float fexp(float x){
  float y = x * 1.44269504f;
  int   ki = __float2int_rn(y);
  float f  = y - (float)ki;
  float p = 1.333355815e-3f;
  p = fmaf(p, f, 9.618129107e-3f);
  p = fmaf(p, f, 5.550410866e-2f);
  p = fmaf(p, f, 2.402265069e-1f);
  p = fmaf(p, f, 6.931471806e-1f);
  p = fmaf(p, f, 1.0f);
  return p * __int_as_float((ki + 127) << 23);
}

// ---------------- GEMM core: CTA 128x128, 8 warps (2x4), warp tile 64x32 ---
// 2 CTAs/SM. BK=64, 256 threads, 3-stage cp.async ring, 8 chunks.
#define SA 72
#define ABYTES (128*144)             // 18432
#define STG2 (2*ABYTES)              // 36864
#define NSTG 3
#define GEMM_SMEM (NSTG*STG2)        // 110592 (x2 CTA = 221184 <= 227KB)
#define NC 8

struct GemmCore {
  uint32_t sbase;
  int m0, n0, tid, lane, warpM, warpN;
  float acc[4][4][4];

  __device__ __forceinline__ void init(uint32_t sb, int m0_, int n0_){
    sbase = sb; m0 = m0_; n0 = n0_;
    tid = threadIdx.x; lane = tid & 31;
    int wid = tid >> 5; warpM = wid >> 2; warpN = wid & 3;
#pragma unroll
    for (int i=0;i<4;i++)
#pragma unroll
      for (int j=0;j<4;j++)
#pragma unroll
        for (int r=0;r<4;r++) acc[i][j][r]=0.f;
  }

  __device__ __forceinline__ void load_chunk(int s, int c,
      const __half* A, const __half* W){
    const int kk0 = c * 64;
    const uint32_t da = sbase + s*STG2;
    const uint32_t db = da + ABYTES;
#pragma unroll
    for (int i=0;i<4;i++){
      int u = tid + i*256;
      int row = u >> 3, cc = u & 7;
      asm volatile("cp.async.cg.shared.global [%0], [%1], 16;"
        :: "r"(da + (uint32_t)(row*144 + cc*16)),
           "l"(A + (size_t)(m0+row)*512 + kk0 + cc*8));
    }
#pragma unroll
    for (int i=0;i<4;i++){
      int u = tid + i*256;
      int row = u >> 3, cc = u & 7;
      asm volatile("cp.async.cg.shared.global [%0], [%1], 16;"
        :: "r"(db + (uint32_t)(row*144 + cc*16)),
           "l"(W + (size_t)(n0+row)*512 + kk0 + cc*8));
    }
    asm volatile("cp.async.commit_group;" ::: "memory");
  }

  __device__ __forceinline__ void compute(int s){
    const uint32_t abase = sbase + s*STG2
        + (uint32_t)((warpM*64 + (lane & 15))*SA*2 + (lane >> 4)*16);
    const uint32_t bbase = sbase + s*STG2 + ABYTES;
    const int n_off = ((lane >> 4) & 1) * 8 + (lane & 7);
    const int k_off = ((lane >> 3) & 1) * 8;
    uint32_t boff[2];
#pragma unroll
    for (int nip=0; nip<2; nip++)
      boff[nip] = bbase + (uint32_t)(((warpN*32 + nip*16 + n_off)*SA + k_off)*2);
#pragma unroll
    for (int k16=0; k16<4; k16++){
      uint32_t af[4][4];
#pragma unroll
      for (int mf=0; mf<4; mf++)
        ldsm4(af[mf], abase + (uint32_t)(mf*16*SA*2) + k16*32);
      uint32_t bf[2][4];
#pragma unroll
      for (int nip=0; nip<2; nip++)
        ldsm4(bf[nip], boff[nip] + k16*32);
#pragma unroll
      for (int mf=0; mf<4; mf++)
#pragma unroll
        for (int nip=0; nip<2; nip++){
          mma16816(acc[mf][2*nip],   af[mf], bf[nip]);
          mma16816(acc[mf][2*nip+1], af[mf], bf[nip]+2);
        }
    }
  }

  __device__ __forceinline__ void run(const __half* A, const __half* W){
    load_chunk(0, 0, A, W);
    load_chunk(1, 1, A, W);
    for (int c=0; c<NC; c++){
      if (c < NC-1) asm volatile("cp.async.wait_group 1;" ::: "memory");
      else          asm volatile("cp.async.wait_group 0;" ::: "memory");
      __syncthreads();
      if (c+2 < NC) load_chunk((c+2)%NSTG, c+2, A, W);
      compute(c%NSTG);
    }
  }

  // fp16 output; relu optional
  __device__ __forceinline__ void epilogue(const float* bias, __half* C16, int relu){
    const int g  = lane >> 2;
    const int tg = lane & 3;
#pragma unroll
    for (int mf=0; mf<4; mf++){
      const int row = m0 + warpM*64 + mf*16 + g;
#pragma unroll
      for (int ni=0; ni<4; ni++){
        const int col = n0 + warpN*32 + ni*8 + tg*2;
        const float b0 = bias[col], b1 = bias[col+1];
        float v[4] = {acc[mf][ni][0]+b0, acc[mf][ni][1]+b1,
                      acc[mf][ni][2]+b0, acc[mf][ni][3]+b1};
        if (relu){
#pragma unroll
          for (int e=0;e<4;e++) v[e] = fmaxf(v[e],0.f);
        }
        *reinterpret_cast<__half2*>(&C16[(size_t)row*512+col]) =
            __halves2half2(__float2half(v[0]), __float2half(v[1]));
        *reinterpret_cast<__half2*>(&C16[(size_t)(row+8)*512+col]) =
            __halves2half2(__float2half(v[2]), __float2half(v[3]));
      }
    }
  }
};

__global__ __launch_bounds__(256,2) void gemm_mma(
    const __half* __restrict__ A, const __half* __restrict__ W,
    const float* __restrict__ bias, __half* __restrict__ C16, int relu)
{
  extern __shared__ __align__(16) char smem_raw[];
  gdc_wait();
  GemmCore core;
  core.init(s2u(smem_raw), blockIdx.y*128, blockIdx.x*128);
  core.run(A, W);
  core.epilogue(bias, C16, relu);
  gdc_launch();
}

// Fused QKV: grid (12, 64); weight = blockIdx.x>>2, n-tile = blockIdx.x&3.
struct QKVArgs {
  const __half *w0,*w1,*w2;
  const float *bias0,*bias1,*bias2;
  __half *c0,*c1,*c2;
};

__global__ __launch_bounds__(256,2) void gemm_qkv(
    const __half* __restrict__ A, QKVArgs a)
{
  extern __shared__ __align__(16) char smem_raw[];
  gdc_wait();
  const int w = blockIdx.x >> 2;
  const __half* W    = (w==0) ? a.w0 : (w==1) ? a.w1 : a.w2;
  const float* bias  = (w==0) ? a.bias0 : (w==1) ? a.bias1 : a.bias2;
  __half* C16        = (w==0) ? a.c0 : (w==1) ? a.c1 : a.c2;
  GemmCore core;
  core.init(s2u(smem_raw), blockIdx.y*128, (blockIdx.x & 3)*128);
  core.run(A, W);
  core.epilogue(bias, C16, 0);
  gdc_launch();
}

// ---------------- prep: 5 weight transposes + x fp32->fp16, one launch -----
struct PrepArgs {
  const float* w[5];
  __half* t[5];
  const float* x;
  __half* x16;
};

__global__ __launch_bounds__(256) void prep_kernel(PrepArgs a)
{
  const int bx = blockIdx.x;
  if (bx < 1280){
    __shared__ float t[32][33];
    const int wsel = bx >> 8;          // 0..4
    const int tile = bx & 255;         // 16x16 tiles
    const int bxx = (tile & 15) * 32;  // n
    const int byy = (tile >> 4) * 32;  // k
    const float* W = a.w[wsel];
    __half* T      = a.t[wsel];
    const int txx = threadIdx.x & 31, tyy = threadIdx.x >> 5;
#pragma unroll
    for (int i=tyy;i<32;i+=8)
      t[i][txx] = W[(size_t)(byy+i)*512 + bxx + txx];
    __syncthreads();
#pragma unroll
    for (int i=tyy;i<32;i+=8)
      T[(size_t)(bxx+i)*512 + byy + txx] = __float2half(t[txx][i]);
  } else {
    int i = (bx - 1280)*256 + threadIdx.x;   // over float4 quads
    float4 v = reinterpret_cast<const float4*>(a.x)[i];
    reinterpret_cast<__half2*>(a.x16)[2*i]   = __halves2half2(__float2half(v.x), __float2half(v.y));
    reinterpret_cast<__half2*>(a.x16)[2*i+1] = __halves2half2(__float2half(v.z), __float2half(v.w));
  }
  gdc_launch();
}

// ---------------- LayerNorm: one warp per row (no smem, no barriers) -------
__global__ __launch_bounds__(256) void ln_f16(
    const __half* __restrict__ hp, const float* __restrict__ g,
    const float* __restrict__ b, __half* __restrict__ h16)
{
  gdc_wait();
  const int w = threadIdx.x >> 5, lane = threadIdx.x & 31;
  const int row = blockIdx.x*8 + w;
  const __half2* hr = reinterpret_cast<const __half2*>(hp + (size_t)row*512);
  float v0[8], v1[8];
  float s = 0.f;
#pragma unroll
  for (int i=0;i<8;i++){
    __half2 hv = hr[lane + i*32];
    v0[i] = __low2float(hv); v1[i] = __high2float(hv);
    s += v0[i] + v1[i];
  }
#pragma unroll
  for (int o=16;o;o>>=1) s += __shfl_xor_sync(0xffffffffu,s,o);
  const float mu = s * (1.f/512.f);
  float q = 0.f;
#pragma unroll
  for (int i=0;i<8;i++){
    v0[i] -= mu; v1[i] -= mu;
    q += v0[i]*v0[i] + v1[i]*v1[i];
  }
#pragma unroll
  for (int o=16;o;o>>=1) q += __shfl_xor_sync(0xffffffffu,q,o);
  const float rstd = rsqrtf(q * (1.f/512.f) + 1e-5f);
  __half2* orow = reinterpret_cast<__half2*>(h16 + (size_t)row*512);
#pragma unroll
  for (int i=0;i<8;i++){
    const int c = 2*(lane + i*32);
    float o0 = v0[i]*rstd*g[c]   + b[c];
    float o1 = v1[i]*rstd*g[c+1] + b[c+1];
    orow[lane + i*32] = __halves2half2(__float2half(o0), __float2half(o1));
  }
  gdc_launch();
}

// ---------------- Tensor-core flash attention (fp16, no-max softmax) -------
// Per CTA: (b, h, 128 q rows). 256 threads, 8 warps. 2 CTAs/SM.
#define QB 144
#define PB 272
#define OQ  0
#define OK0 18432
#define OK1 36864
#define OV  55296
#define OP  73728
#define OLP 108544
#define AT_SMEM (OLP + 1024)

__device__ __forceinline__ void at_load_tile(uint32_t sdst,
    const __half* __restrict__ g, int row0, int col0, int tid)
{
  int row = tid >> 1, half = tid & 1;
  uint32_t d = sdst + (uint32_t)(row*QB + half*64);
  const __half* s = g + (size_t)(row0+row)*512 + col0 + half*32;
#pragma unroll
  for (int j=0;j<4;j++)
    asm volatile("cp.async.cg.shared.global [%0], [%1], 16;" :: "r"(d + j*16), "l"(s + j*8));
}

__global__ __launch_bounds__(256,2) void attn_mma(
    const __half* __restrict__ q16, const __half* __restrict__ k16,
    const __half* __restrict__ v16,
    const float* __restrict__ adj, const int* __restrict__ use_adj,
    __half* __restrict__ c16)
{
  extern __shared__ __align__(16) char sm8[];
  gdc_wait();
  const uint32_t sb = s2u(sm8);
  float* lp = reinterpret_cast<float*>(sm8 + OLP);

  const int tid = threadIdx.x, lane = tid & 31, wid = tid >> 5;
  const int warpM = wid >> 1, warpN = wid & 1;
  const int q0 = blockIdx.x * 128;
  const int hh = blockIdx.y, bb = blockIdx.z;
  const int ua = use_adj[0];
  const int col0 = hh * 64;
  const int rowg0 = bb * 512;

  at_load_tile(sb+OQ, q16, rowg0+q0, col0, tid);
  lp[tid] = 0.f;

  float oacc[2][4][4];
#pragma unroll
  for (int i=0;i<2;i++)
#pragma unroll
    for (int j=0;j<4;j++)
#pragma unroll
      for (int e=0;e<4;e++) oacc[i][j][e]=0.f;

  const uint32_t a_off  = (uint32_t)((lane&15)*QB + (lane>>4)*16);
  const uint32_t b_off  = (uint32_t)((((lane>>4)&1)*8 + (lane&7))*QB + ((lane>>3)&1)*16);
  const uint32_t ap_off = (uint32_t)((lane&15)*PB + (lane>>4)*16);

  const int r0 = warpM*32 + (lane>>2);
  const int cb = warpN*64 + 2*(lane&3);

  for (int kb=0; kb<4; kb++){
    const int krow0 = rowg0 + kb*128;
    if (kb == 0){
      at_load_tile(sb+OK0, k16, krow0, col0, tid);
      at_load_tile(sb+OV,  v16, krow0, col0, tid);
      asm volatile("cp.async.commit_group;" ::: "memory");
      asm volatile("cp.async.wait_group 0;" ::: "memory");
      __syncthreads();
    }

    // ---- S = Q K^T ----
    float sacc[2][8][4];
#pragma unroll
    for (int i=0;i<2;i++)
#pragma unroll
      for (int j=0;j<8;j++)
#pragma unroll
        for (int e=0;e<4;e++) sacc[i][j][e]=0.f;

    {
      const uint32_t qb_ = sb + OQ + (uint32_t)(warpM*32*QB) + a_off;
      const uint32_t kb_ = sb + ((kb&1) ? OK1 : OK0) + (uint32_t)(warpN*64*QB) + b_off;
#pragma unroll
      for (int k16i=0;k16i<4;k16i++){
        uint32_t af[2][4];
        ldsm4(af[0], qb_ + k16i*32);
        ldsm4(af[1], qb_ + 16*QB + k16i*32);
#pragma unroll
        for (int nf=0;nf<4;nf++){
          uint32_t bf[4];
          ldsm4(bf, kb_ + (uint32_t)(nf*16*QB) + k16i*32);
          mma16816(sacc[0][2*nf],   af[0], bf);
          mma16816(sacc[0][2*nf+1], af[0], bf+2);
          mma16816(sacc[1][2*nf],   af[1], bf);
          mma16816(sacc[1][2*nf+1], af[1], bf+2);
        }
      }
    }

    // ---- scale*adj, exp, row sums, store P fp16 ----
#pragma unroll
    for (int mi=0;mi<2;mi++){
      const int rr = r0 + mi*16;
      float rs0 = 0.f, rs8 = 0.f;
#pragma unroll
      for (int nf=0;nf<8;nf++){
        const int cc = cb + nf*8;
        float m0=1.f,m1=1.f,m2=1.f,m3=1.f;
        if (ua){
          const float* ar = adj + ((size_t)(rowg0+q0+rr))*512 + kb*128 + cc;
          float2 a01 = *reinterpret_cast<const float2*>(ar);
          float2 a23 = *reinterpret_cast<const float2*>(ar + 8*512);
          m0=a01.x; m1=a01.y; m2=a23.x; m3=a23.y;
        }
        float p0 = fexp(sacc[mi][nf][0]*0.125f*m0);
        float p1 = fexp(sacc[mi][nf][1]*0.125f*m1);
        float p2 = fexp(sacc[mi][nf][2]*0.125f*m2);
        float p3 = fexp(sacc[mi][nf][3]*0.125f*m3);
        rs0 += p0+p1;  rs8 += p2+p3;
        __half2 t0 = __halves2half2(__float2half(p0), __float2half(p1));
        __half2 t1 = __halves2half2(__float2half(p2), __float2half(p3));
        uint32_t ph01 = *reinterpret_cast<uint32_t*>(&t0);
        uint32_t ph23 = *reinterpret_cast<uint32_t*>(&t1);
        uint32_t pa = sb + OP + (uint32_t)(rr*PB + cc*2);
        asm volatile("st.shared.b32 [%0], %1;" :: "r"(pa), "r"(ph01));
        asm volatile("st.shared.b32 [%0], %1;" :: "r"(pa + 8*PB), "r"(ph23));
      }
      rs0 += __shfl_xor_sync(0xffffffffu, rs0, 1);
      rs0 += __shfl_xor_sync(0xffffffffu, rs0, 2);
      rs8 += __shfl_xor_sync(0xffffffffu, rs8, 1);
      rs8 += __shfl_xor_sync(0xffffffffu, rs8, 2);
      if ((lane&3)==0){
        lp[warpN*128 + rr]     += rs0;
        lp[warpN*128 + rr + 8] += rs8;
      }
    }
    __syncthreads();   // P visible; K[kb&1] free

    if (kb < 3){       // prefetch next K into other buffer while PV runs
      at_load_tile(sb + ((kb&1) ? OK0 : OK1), k16, krow0+128, col0, tid);
      asm volatile("cp.async.commit_group;" ::: "memory");
    }

    // ---- O += P V, V^T via ldmatrix.trans ----
    {
      const uint32_t pb2 = sb + OP + (uint32_t)(warpM*32*PB) + ap_off;
      const uint32_t vb2 = sb + OV + (uint32_t)((lane&15)*QB + (warpN*32 + (lane>>4)*8)*2);
#pragma unroll
      for (int k16i=0;k16i<8;k16i++){
        uint32_t af[2][4];
        ldsm4(af[0], pb2 + k16i*32);
        ldsm4(af[1], pb2 + 16*PB + k16i*32);
#pragma unroll
        for (int nf=0;nf<2;nf++){
          uint32_t bf[4];
          ldsm4t(bf, vb2 + (uint32_t)(k16i*16*QB) + (uint32_t)(nf*16*2));
          mma16816(oacc[0][2*nf],   af[0], bf);
          mma16816(oacc[0][2*nf+1], af[0], bf+2);
          mma16816(oacc[1][2*nf],   af[1], bf);
          mma16816(oacc[1][2*nf+1], af[1], bf+2);
        }
      }
    }
    __syncthreads();   // V reads complete

    if (kb < 3){
      at_load_tile(sb+OV, v16, krow0+128, col0, tid);
      asm volatile("cp.async.commit_group;" ::: "memory");
      asm volatile("cp.async.wait_group 0;" ::: "memory");
      __syncthreads();
    }
  }

  // ---- epilogue: normalize, store fp16 ctx ----
  if (tid < 128) lp[tid] = 1.f / (lp[tid] + lp[128 + tid]);
  __syncthreads();
#pragma unroll
  for (int mi=0;mi<2;mi++){
    const int rr = r0 + mi*16;
    const float inv0 = lp[rr], inv8 = lp[rr+8];
    const size_t rga = (size_t)(rowg0 + q0 + rr);
#pragma unroll
    for (int nf=0;nf<4;nf++){
      const int colg = col0 + warpN*32 + nf*8 + 2*(lane&3);
      *reinterpret_cast<__half2*>(&c16[rga*512 + colg]) =
          __halves2half2(__float2half(oacc[mi][nf][0]*inv0),
                         __float2half(oacc[mi][nf][1]*inv0));
      *reinterpret_cast<__half2*>(&c16[(rga+8)*512 + colg]) =
          __halves2half2(__float2half(oacc[mi][nf][2]*inv8),
                         __float2half(oacc[mi][nf][3]*inv8));
    }
  }
  gdc_launch();
}

// ---------------- Gate + blend: out = c*x + (1-c)*h2 (h2 fp16) -------------
__global__ void gate_kernel(const float* __restrict__ x, const __half* __restrict__ h2,
    const float* __restrict__ gw, const float* __restrict__ gb, float* __restrict__ out)
{
  gdc_wait();
  const int w = threadIdx.x>>5, lane = threadIdx.x&31;
  const int row = blockIdx.x*8 + w;
  const float* xr = x  + (size_t)row*512;
  const __half* hr = h2 + (size_t)row*512;
  float hf[16];
  float s = 0.f;
#pragma unroll
  for (int i=0;i<16;i++){
    int c = i*32 + lane;
    hf[i] = __half2float(hr[c]);
    s += xr[c]*gw[c] + hf[i]*gw[512+c];
  }
#pragma unroll
  for (int off=16;off;off>>=1) s += __shfl_xor_sync(0xffffffffu,s,off);
  s += gb[0];
  float coeff = 1.f/(1.f+__expf(-s));
  float* orow = out + (size_t)row*512;
#pragma unroll
  for (int i=0;i<16;i++){
    int c = i*32+lane;
    orow[c] = coeff*xr[c] + (1.f-coeff)*hf[i];
  }
}

// ---------------- launch ---------------------------------------------------
extern "C" void kernel_launch(void* const* d_in, const int* in_sizes, int n_in,
                              void* d_out, int out_size)
{
  const float* x   = (const float*)d_in[0];
  const float* adj = (const float*)d_in[1];
  const float* W_w = (const float*)d_in[2];
  const float* W_b = (const float*)d_in[3];
  const float* lng = (const float*)d_in[4];
  const float* lnb = (const float*)d_in[5];
  const float* Wq  = (const float*)d_in[6];
  const float* bq  = (const float*)d_in[7];
  const float* Wk  = (const float*)d_in[8];
  const float* bk  = (const float*)d_in[9];
  const float* Wv  = (const float*)d_in[10];
  const float* bv  = (const float*)d_in[11];
  const float* Wo  = (const float*)d_in[12];
  const float* bo  = (const float*)d_in[13];
  const float* gw  = (const float*)d_in[14];
  const float* gbb = (const float*)d_in[15];
  const int*   ua  = (const int*)d_in[16];
  float* out = (float*)d_out;

  __half *x16,*hp16,*h16,*q16,*k16,*v16,*c16,*h2_16,*ww,*wq,*wk,*wv,*wo;
  cudaGetSymbolAddress((void**)&x16,  g_x16);
  cudaGetSymbolAddress((void**)&hp16, g_hp16);
  cudaGetSymbolAddress((void**)&h16,  g_h16);
  cudaGetSymbolAddress((void**)&q16,  g_q16);
  cudaGetSymbolAddress((void**)&k16,  g_k16);
  cudaGetSymbolAddress((void**)&v16,  g_v16);
  cudaGetSymbolAddress((void**)&c16,  g_c16);
  cudaGetSymbolAddress((void**)&h2_16,g_h2_16);
  cudaGetSymbolAddress((void**)&ww,   g_ww);
  cudaGetSymbolAddress((void**)&wq,   g_wq);
  cudaGetSymbolAddress((void**)&wk,   g_wk);
  cudaGetSymbolAddress((void**)&wv,   g_wv);
  cudaGetSymbolAddress((void**)&wo,   g_wo);

  cudaFuncSetAttribute(gemm_mma, cudaFuncAttributeMaxDynamicSharedMemorySize, GEMM_SMEM);
  cudaFuncSetAttribute(gemm_qkv, cudaFuncAttributeMaxDynamicSharedMemorySize, GEMM_SMEM);
  cudaFuncSetAttribute(attn_mma, cudaFuncAttributeMaxDynamicSharedMemorySize, AT_SMEM);

  QKVArgs qa;
  qa.w0=wq; qa.w1=wk; qa.w2=wv;
  qa.bias0=bq; qa.bias1=bk; qa.bias2=bv;
  qa.c0=q16; qa.c1=k16; qa.c2=v16;

  PrepArgs pa;
  pa.w[0]=W_w; pa.w[1]=Wq; pa.w[2]=Wk; pa.w[3]=Wv; pa.w[4]=Wo;
  pa.t[0]=ww; pa.t[1]=wq; pa.t[2]=wk; pa.t[3]=wv; pa.t[4]=wo;
  pa.x = x; pa.x16 = x16;

  // PDL attribute: allow each launch to begin while its predecessor drains.
  cudaLaunchAttribute at[1];
  at[0].id = cudaLaunchAttributeProgrammaticStreamSerialization;
  at[0].val.programmaticStreamSerializationAllowed = 1;

  {
    cudaLaunchConfig_t cfg = {};
    cfg.gridDim = dim3(5376); cfg.blockDim = dim3(256);
    cudaLaunchKernelEx(&cfg, prep_kernel, pa);
  }
  {
    cudaLaunchConfig_t cfg = {};
    cfg.gridDim = dim3(4,64); cfg.blockDim = dim3(256);
    cfg.dynamicSmemBytes = GEMM_SMEM;
    cfg.attrs = at; cfg.numAttrs = 1;
    cudaLaunchKernelEx(&cfg, gemm_mma, (const __half*)x16, (const __half*)ww,
                       (const float*)W_b, (__half*)hp16, 0);
  }
  {
    cudaLaunchConfig_t cfg = {};
    cfg.gridDim = dim3(1024); cfg.blockDim = dim3(256);
    cfg.attrs = at; cfg.numAttrs = 1;
    cudaLaunchKernelEx(&cfg, ln_f16, (const __half*)hp16, (const float*)lng,
                       (const float*)lnb, (__half*)h16);
  }
  {
    cudaLaunchConfig_t cfg = {};
    cfg.gridDim = dim3(12,64); cfg.blockDim = dim3(256);
    cfg.dynamicSmemBytes = GEMM_SMEM;
    cfg.attrs = at; cfg.numAttrs = 1;
    cudaLaunchKernelEx(&cfg, gemm_qkv, (const __half*)h16, qa);
  }
  {
    cudaLaunchConfig_t cfg = {};
    cfg.gridDim = dim3(4,8,16); cfg.blockDim = dim3(256);
    cfg.dynamicSmemBytes = AT_SMEM;
    cfg.attrs = at; cfg.numAttrs = 1;
    cudaLaunchKernelEx(&cfg, attn_mma, (const __half*)q16, (const __half*)k16,
                       (const __half*)v16, (const float*)adj, (const int*)ua,
                       (__half*)c16);
  }
  {
    cudaLaunchConfig_t cfg = {};
    cfg.gridDim = dim3(4,64); cfg.blockDim = dim3(256);
    cfg.dynamicSmemBytes = GEMM_SMEM;
    cfg.attrs = at; cfg.numAttrs = 1;
    cudaLaunchKernelEx(&cfg, gemm_mma, (const __half*)c16, (const __half*)wo,
                       (const float*)bo, (__half*)h2_16, 1);
  }
  {
    cudaLaunchConfig_t cfg = {};
    cfg.gridDim = dim3(1024); cfg.blockDim = dim3(256);
    cfg.attrs = at; cfg.numAttrs = 1;
    cudaLaunchKernelEx(&cfg, gate_kernel, (const float*)x, (const __half*)h2_16,
                       (const float*)gw, (const float*)gbb, (float*)out);
  }
}